// round 2
// baseline (speedup 1.0000x reference)
#include <cuda_runtime.h>
#include <cstdint>

// Problem constants
#define BB 4
#define NN 2048
#define CC 1024
#define HH 16
#define DD 64
#define MM (BB*NN)          // 8192 token rows
#define EMB 1024
#define EPSV 1e-5f

// ---------------- scratch (device globals; no allocation allowed) ----------
__device__ float g_se[(size_t)MM * 2048];   // 64 MB
__device__ float g_h [(size_t)MM * 1024];   // 32 MB
__device__ float g_qkv[(size_t)MM * 3072];  // 96 MB
__device__ float g_o [(size_t)MM * 1024];   // 32 MB

// ---------------- generic SGEMM: C = A(MxK) * B(NxK)^T  -------------------
// EPI 0: C = acc + bias[n]   (extra = bias, length N)
// EPI 1: C = acc
// EPI 2: C = acc + extra[m*N+n]  (residual)
template<int EPI>
__global__ void __launch_bounds__(256, 4)
sgemm_nt(const float* __restrict__ A, const float* __restrict__ B,
         float* __restrict__ C, int N, int K, const float* __restrict__ extra)
{
    __shared__ float As[16][65];  // As[k][m]
    __shared__ float Bs[16][65];  // Bs[k][n]

    const int tid = threadIdx.x;
    const int tx = tid & 15;      // 0..15 -> n groups
    const int ty = tid >> 4;      // 0..15 -> m groups
    const int m0 = blockIdx.y * 64;
    const int n0 = blockIdx.x * 64;

    const int lm  = tid >> 2;          // 0..63
    const int lk4 = (tid & 3) * 4;     // 0,4,8,12

    const float* Aptr = A + (size_t)(m0 + lm) * K + lk4;
    const float* Bptr = B + (size_t)(n0 + lm) * K + lk4;

    float acc[4][4];
    #pragma unroll
    for (int i = 0; i < 4; i++)
        #pragma unroll
        for (int j = 0; j < 4; j++) acc[i][j] = 0.f;

    for (int k0 = 0; k0 < K; k0 += 16) {
        float4 a = *(const float4*)(Aptr + k0);
        float4 b = *(const float4*)(Bptr + k0);
        As[lk4 + 0][lm] = a.x; As[lk4 + 1][lm] = a.y;
        As[lk4 + 2][lm] = a.z; As[lk4 + 3][lm] = a.w;
        Bs[lk4 + 0][lm] = b.x; Bs[lk4 + 1][lm] = b.y;
        Bs[lk4 + 2][lm] = b.z; Bs[lk4 + 3][lm] = b.w;
        __syncthreads();

        #pragma unroll
        for (int k = 0; k < 16; k++) {
            float ra[4], rb[4];
            #pragma unroll
            for (int i = 0; i < 4; i++) ra[i] = As[k][ty * 4 + i];
            #pragma unroll
            for (int j = 0; j < 4; j++) rb[j] = Bs[k][tx * 4 + j];
            #pragma unroll
            for (int i = 0; i < 4; i++)
                #pragma unroll
                for (int j = 0; j < 4; j++)
                    acc[i][j] = fmaf(ra[i], rb[j], acc[i][j]);
        }
        __syncthreads();
    }

    #pragma unroll
    for (int i = 0; i < 4; i++) {
        const int row = m0 + ty * 4 + i;
        const size_t base = (size_t)row * N + n0 + tx * 4;
        float4 r;
        if (EPI == 0) {
            const float* bp = extra + n0 + tx * 4;
            r.x = acc[i][0] + bp[0];
            r.y = acc[i][1] + bp[1];
            r.z = acc[i][2] + bp[2];
            r.w = acc[i][3] + bp[3];
        } else if (EPI == 2) {
            float4 e = *(const float4*)(extra + base);
            r.x = acc[i][0] + e.x;
            r.y = acc[i][1] + e.y;
            r.z = acc[i][2] + e.z;
            r.w = acc[i][3] + e.w;
        } else {
            r.x = acc[i][0]; r.y = acc[i][1]; r.z = acc[i][2]; r.w = acc[i][3];
        }
        *(float4*)(C + base) = r;
    }
}

// ---------------- LayerNorm(x) * (1+scale) + shift -------------------------
__global__ void ln_film_kernel(const float* __restrict__ x,
                               const float* __restrict__ se,
                               float* __restrict__ h)
{
    const int m = blockIdx.x;
    const float* xr = x + (size_t)m * CC;
    const float* sc = se + (size_t)m * (2 * CC);
    float* hr = h + (size_t)m * CC;

    float v[4];
    float s = 0.f, s2 = 0.f;
    #pragma unroll
    for (int e = 0; e < 4; e++) {
        v[e] = xr[threadIdx.x + e * 256];
        s += v[e];
        s2 += v[e] * v[e];
    }
    // block reduce (256 threads = 8 warps)
    __shared__ float shs[8], shs2[8], bcast[2];
    const int lane = threadIdx.x & 31, w = threadIdx.x >> 5;
    #pragma unroll
    for (int o = 16; o; o >>= 1) {
        s  += __shfl_xor_sync(0xffffffffu, s,  o);
        s2 += __shfl_xor_sync(0xffffffffu, s2, o);
    }
    if (lane == 0) { shs[w] = s; shs2[w] = s2; }
    __syncthreads();
    if (w == 0) {
        float a  = (lane < 8) ? shs[lane]  : 0.f;
        float a2 = (lane < 8) ? shs2[lane] : 0.f;
        #pragma unroll
        for (int o = 4; o; o >>= 1) {
            a  += __shfl_xor_sync(0xffffffffu, a,  o);
            a2 += __shfl_xor_sync(0xffffffffu, a2, o);
        }
        if (lane == 0) { bcast[0] = a; bcast[1] = a2; }
    }
    __syncthreads();
    const float mu  = bcast[0] * (1.f / CC);
    const float var = bcast[1] * (1.f / CC) - mu * mu;
    const float rs  = rsqrtf(var + EPSV);

    #pragma unroll
    for (int e = 0; e < 4; e++) {
        const int c = threadIdx.x + e * 256;
        hr[c] = (v[e] - mu) * rs * (1.f + sc[c]) + sc[c + CC];
    }
}

// ---------------- per-head LayerNorm of q and k (D=64 per segment) ---------
__global__ void qk_ln_kernel(float* __restrict__ qkv)
{
    const int seg  = blockIdx.x * 8 + (threadIdx.x >> 5);  // 8192*32 segments
    const int lane = threadIdx.x & 31;
    const int m = seg >> 5;
    const int r = seg & 31;                       // 0..15 q heads, 16..31 k heads
    float* base = qkv + (size_t)m * 3072 + (r >> 4) * 1024 + (r & 15) * 64;

    float a = base[lane];
    float b = base[lane + 32];
    float s = a + b, s2 = a * a + b * b;
    #pragma unroll
    for (int o = 16; o; o >>= 1) {
        s  += __shfl_xor_sync(0xffffffffu, s,  o);
        s2 += __shfl_xor_sync(0xffffffffu, s2, o);
    }
    const float mu  = s * (1.f / 64.f);
    const float var = s2 * (1.f / 64.f) - mu * mu;
    const float rs  = rsqrtf(var + EPSV);
    base[lane]      = (a - mu) * rs;
    base[lane + 32] = (b - mu) * rs;
}

// ---------------- flash attention (fp32, BM=BN=64, D=64) -------------------
__global__ void __launch_bounds__(256, 4)
flash_kernel(const float* __restrict__ qkv, float* __restrict__ o)
{
    constexpr int BMQ = 64, BNK = 64;
    __shared__ float Qs[BMQ * 64];        // Qs[r*64+c], broadcast reads -> no pad
    __shared__ float KVs[BNK * 64];       // xor-swizzled: [r*64 + (c ^ (r&31))]
    __shared__ float Ps[BMQ * 64];        // broadcast reads

    const int bh = blockIdx.y;
    const int b  = bh >> 4;
    const int h  = bh & 15;
    const int n0 = blockIdx.x * BMQ;

    const float* qb = qkv + (size_t)b * NN * 3072 + h * 64;
    const float* kb = qb + 1024;
    const float* vb = qb + 2048;

    const int tid = threadIdx.x;
    const int tx = tid & 15;   // column group (16 x 4)
    const int ty = tid >> 4;   // row group    (16 x 4)

    // load Q tile
    for (int idx = tid; idx < BMQ * 64; idx += 256) {
        const int r = idx >> 6, c = idx & 63;
        Qs[r * 64 + c] = qb[(size_t)(n0 + r) * 3072 + c];
    }

    float acc[4][4];
    float mrow[4], lrow[4];
    #pragma unroll
    for (int i = 0; i < 4; i++) {
        mrow[i] = -1e30f; lrow[i] = 0.f;
        #pragma unroll
        for (int j = 0; j < 4; j++) acc[i][j] = 0.f;
    }

    const float sm = 0.125f;  // 1/sqrt(64)

    for (int kt = 0; kt < NN; kt += BNK) {
        __syncthreads();  // prior PV reads of KVs done (and Q load on iter 0)
        // load K tile (swizzled)
        for (int idx = tid; idx < BNK * 64; idx += 256) {
            const int r = idx >> 6, c = idx & 63;
            KVs[r * 64 + (c ^ (r & 31))] = kb[(size_t)(kt + r) * 3072 + c];
        }
        __syncthreads();

        float s[4][4];
        #pragma unroll
        for (int i = 0; i < 4; i++)
            #pragma unroll
            for (int j = 0; j < 4; j++) s[i][j] = 0.f;

        #pragma unroll 8
        for (int kk = 0; kk < 64; kk++) {
            float ra[4], rb[4];
            #pragma unroll
            for (int i = 0; i < 4; i++) ra[i] = Qs[(ty * 4 + i) * 64 + kk];
            #pragma unroll
            for (int j = 0; j < 4; j++) {
                const int col = tx * 4 + j;
                rb[j] = KVs[col * 64 + (kk ^ (col & 31))];
            }
            #pragma unroll
            for (int i = 0; i < 4; i++)
                #pragma unroll
                for (int j = 0; j < 4; j++)
                    s[i][j] = fmaf(ra[i], rb[j], s[i][j]);
        }

        // online softmax per row (row groups shared across 16 lanes of same ty)
        #pragma unroll
        for (int i = 0; i < 4; i++) {
            float mx = -1e30f;
            #pragma unroll
            for (int j = 0; j < 4; j++) { s[i][j] *= sm; mx = fmaxf(mx, s[i][j]); }
            #pragma unroll
            for (int o = 8; o; o >>= 1)
                mx = fmaxf(mx, __shfl_xor_sync(0xffffffffu, mx, o));
            const float mnew = fmaxf(mrow[i], mx);
            const float corr = __expf(mrow[i] - mnew);
            mrow[i] = mnew;
            lrow[i] *= corr;
            #pragma unroll
            for (int j = 0; j < 4; j++) acc[i][j] *= corr;
            float rsum = 0.f;
            #pragma unroll
            for (int j = 0; j < 4; j++) {
                const float p = __expf(s[i][j] - mnew);
                Ps[(ty * 4 + i) * 64 + tx * 4 + j] = p;
                rsum += p;
            }
            #pragma unroll
            for (int o = 8; o; o >>= 1)
                rsum += __shfl_xor_sync(0xffffffffu, rsum, o);
            lrow[i] += rsum;
        }
        __syncthreads();   // all done reading K from KVs

        // load V tile into same buffer (swizzled)
        for (int idx = tid; idx < BNK * 64; idx += 256) {
            const int r = idx >> 6, c = idx & 63;
            KVs[r * 64 + (c ^ (r & 31))] = vb[(size_t)(kt + r) * 3072 + c];
        }
        __syncthreads();

        // O += P * V
        #pragma unroll 8
        for (int n = 0; n < 64; n++) {
            float rp[4], rv[4];
            #pragma unroll
            for (int i = 0; i < 4; i++) rp[i] = Ps[(ty * 4 + i) * 64 + n];
            #pragma unroll
            for (int j = 0; j < 4; j++) {
                const int col = tx * 4 + j;
                rv[j] = KVs[n * 64 + (col ^ (n & 31))];
            }
            #pragma unroll
            for (int i = 0; i < 4; i++)
                #pragma unroll
                for (int j = 0; j < 4; j++)
                    acc[i][j] = fmaf(rp[i], rv[j], acc[i][j]);
        }
    }

    // epilogue: o[b][n][h*64 + d]
    #pragma unroll
    for (int i = 0; i < 4; i++) {
        const float inv = 1.f / lrow[i];
        const int row = n0 + ty * 4 + i;
        float* orow = o + (size_t)(b * NN + row) * CC + h * 64 + tx * 4;
        float4 r;
        r.x = acc[i][0] * inv; r.y = acc[i][1] * inv;
        r.z = acc[i][2] * inv; r.w = acc[i][3] * inv;
        *(float4*)orow = r;
    }
}

// ---------------- launcher -------------------------------------------------
extern "C" void kernel_launch(void* const* d_in, const int* in_sizes, int n_in,
                              void* d_out, int out_size)
{
    const float* x      = (const float*)d_in[0];
    const float* emb    = (const float*)d_in[1];
    const float* W_emb  = (const float*)d_in[2];
    const float* b_emb  = (const float*)d_in[3];
    const float* W_proj = (const float*)d_in[4];
    const float* W_out  = (const float*)d_in[5];
    float* out = (float*)d_out;

    float *se, *h, *qkv, *o;
    cudaGetSymbolAddress((void**)&se,  g_se);
    cudaGetSymbolAddress((void**)&h,   g_h);
    cudaGetSymbolAddress((void**)&qkv, g_qkv);
    cudaGetSymbolAddress((void**)&o,   g_o);

    // 1) se = emb @ W_emb^T + b_emb         (8192 x 2048 x 1024)
    sgemm_nt<0><<<dim3(2048 / 64, MM / 64), 256>>>(emb, W_emb, se, 2048, EMB, b_emb);
    // 2) h = LN(x)*(1+scale)+shift
    ln_film_kernel<<<MM, 256>>>(x, se, h);
    // 3) qkv = h @ W_proj^T                 (8192 x 3072 x 1024)
    sgemm_nt<1><<<dim3(3072 / 64, MM / 64), 256>>>(h, W_proj, qkv, 3072, CC, nullptr);
    // 4) per-head LN of q and k
    qk_ln_kernel<<<(MM * 32) / 8, 256>>>(qkv);
    // 5) flash attention -> o (B,N,C layout)
    flash_kernel<<<dim3(NN / 64, BB * HH), 256>>>(qkv, o);
    // 6) out = o + o @ W_out^T              (8192 x 1024 x 1024)
    sgemm_nt<2><<<dim3(1024 / 64, MM / 64), 256>>>(o, W_out, out, 1024, CC, o);
}

// round 3
// speedup vs baseline: 1.5687x; 1.5687x over previous
#include <cuda_runtime.h>
#include <cuda_bf16.h>
#include <cstdint>

// Problem constants
#define BB 4
#define NN 2048
#define CC 1024
#define HH 16
#define DD 64
#define MM (BB*NN)          // 8192 token rows
#define EMB 1024
#define EPSV 1e-5f

// ---------------- scratch (device globals; no allocation allowed) ----------
__device__ float g_se[(size_t)MM * 2048];   // 64 MB
__device__ float g_h [(size_t)MM * 1024];   // 32 MB
__device__ float g_qkv[(size_t)MM * 3072];  // 96 MB
__device__ float g_o [(size_t)MM * 1024];   // 32 MB

// ---------------- bf16x3 tensor-core GEMM: C = A(MxK) * B(NxK)^T ----------
// EPI 0: C = acc + bias[n]
// EPI 1: C = acc
// EPI 2: C = acc + extra[m*N+n]  (residual)
//
// Block tile 128(M) x 64(N) x 32(K); 8 warps (4x2), warp tile 32x32.
// Precision: a*b ~= ah*bh + ah*bl + al*bh  (fp32 accumulate) -> ~fp32 quality.

__device__ __forceinline__ void mma16816(float* c, const uint32_t* a, const uint32_t* b)
{
    asm volatile(
        "mma.sync.aligned.m16n8k16.row.col.f32.bf16.bf16.f32 "
        "{%0,%1,%2,%3}, {%4,%5,%6,%7}, {%8,%9}, {%0,%1,%2,%3};\n"
        : "+f"(c[0]), "+f"(c[1]), "+f"(c[2]), "+f"(c[3])
        : "r"(a[0]), "r"(a[1]), "r"(a[2]), "r"(a[3]), "r"(b[0]), "r"(b[1]));
}

#define LDA 40  // padded row stride (bf16 elems): 80B = 20 banks -> conflict-free frags

template<int EPI>
__global__ void __launch_bounds__(256, 2)
bgemm_nt(const float* __restrict__ A, const float* __restrict__ B,
         float* __restrict__ C, int N, int K, const float* __restrict__ extra)
{
    __shared__ __nv_bfloat16 Ah[128 * LDA], Al[128 * LDA];
    __shared__ __nv_bfloat16 Bh[64 * LDA],  Bl[64 * LDA];

    const int tid  = threadIdx.x;
    const int lane = tid & 31;
    const int wid  = tid >> 5;
    const int g    = lane >> 2;     // 0..7
    const int t    = lane & 3;      // 0..3
    const int wm   = wid >> 1;      // 0..3 -> m offset wm*32
    const int wn   = wid & 1;       // 0..1 -> n offset wn*32

    const int m0 = blockIdx.y * 128;
    const int n0 = blockIdx.x * 64;

    const int lr = tid >> 3;        // 0..31 loader row
    const int lc = (tid & 7) * 4;   // 0,4,...,28 loader col

    float acc[2][4][4];
    #pragma unroll
    for (int mi = 0; mi < 2; mi++)
        #pragma unroll
        for (int ni = 0; ni < 4; ni++)
            #pragma unroll
            for (int e = 0; e < 4; e++) acc[mi][ni][e] = 0.f;

    for (int k0 = 0; k0 < K; k0 += 32) {
        // ---- load + split A tile (128x32) ----
        #pragma unroll
        for (int i = 0; i < 4; i++) {
            const int r = lr + 32 * i;
            float4 v = *(const float4*)(A + (size_t)(m0 + r) * K + k0 + lc);
            __nv_bfloat16 hx = __float2bfloat16_rn(v.x);
            __nv_bfloat16 hy = __float2bfloat16_rn(v.y);
            __nv_bfloat16 hz = __float2bfloat16_rn(v.z);
            __nv_bfloat16 hw = __float2bfloat16_rn(v.w);
            __nv_bfloat162 h01; h01.x = hx; h01.y = hy;
            __nv_bfloat162 h23; h23.x = hz; h23.y = hw;
            __nv_bfloat162 l01, l23;
            l01.x = __float2bfloat16_rn(v.x - __bfloat162float(hx));
            l01.y = __float2bfloat16_rn(v.y - __bfloat162float(hy));
            l23.x = __float2bfloat16_rn(v.z - __bfloat162float(hz));
            l23.y = __float2bfloat16_rn(v.w - __bfloat162float(hw));
            *(__nv_bfloat162*)&Ah[r * LDA + lc]     = h01;
            *(__nv_bfloat162*)&Ah[r * LDA + lc + 2] = h23;
            *(__nv_bfloat162*)&Al[r * LDA + lc]     = l01;
            *(__nv_bfloat162*)&Al[r * LDA + lc + 2] = l23;
        }
        // ---- load + split B tile (64x32) ----
        #pragma unroll
        for (int i = 0; i < 2; i++) {
            const int r = lr + 32 * i;
            float4 v = *(const float4*)(B + (size_t)(n0 + r) * K + k0 + lc);
            __nv_bfloat16 hx = __float2bfloat16_rn(v.x);
            __nv_bfloat16 hy = __float2bfloat16_rn(v.y);
            __nv_bfloat16 hz = __float2bfloat16_rn(v.z);
            __nv_bfloat16 hw = __float2bfloat16_rn(v.w);
            __nv_bfloat162 h01; h01.x = hx; h01.y = hy;
            __nv_bfloat162 h23; h23.x = hz; h23.y = hw;
            __nv_bfloat162 l01, l23;
            l01.x = __float2bfloat16_rn(v.x - __bfloat162float(hx));
            l01.y = __float2bfloat16_rn(v.y - __bfloat162float(hy));
            l23.x = __float2bfloat16_rn(v.z - __bfloat162float(hz));
            l23.y = __float2bfloat16_rn(v.w - __bfloat162float(hw));
            *(__nv_bfloat162*)&Bh[r * LDA + lc]     = h01;
            *(__nv_bfloat162*)&Bh[r * LDA + lc + 2] = h23;
            *(__nv_bfloat162*)&Bl[r * LDA + lc]     = l01;
            *(__nv_bfloat162*)&Bl[r * LDA + lc + 2] = l23;
        }
        __syncthreads();

        #pragma unroll
        for (int kk = 0; kk < 32; kk += 16) {
            // A fragments (hi & lo) for 2 m16 blocks
            uint32_t afh[2][4], afl[2][4];
            #pragma unroll
            for (int mi = 0; mi < 2; mi++) {
                const int r0 = (wm * 32 + mi * 16 + g) * LDA + kk + t * 2;
                const int r1 = r0 + 8 * LDA;
                afh[mi][0] = *(const uint32_t*)&Ah[r0];
                afh[mi][1] = *(const uint32_t*)&Ah[r1];
                afh[mi][2] = *(const uint32_t*)&Ah[r0 + 8];
                afh[mi][3] = *(const uint32_t*)&Ah[r1 + 8];
                afl[mi][0] = *(const uint32_t*)&Al[r0];
                afl[mi][1] = *(const uint32_t*)&Al[r1];
                afl[mi][2] = *(const uint32_t*)&Al[r0 + 8];
                afl[mi][3] = *(const uint32_t*)&Al[r1 + 8];
            }
            // B fragments (hi & lo) for 4 n8 blocks
            uint32_t bfh[4][2], bfl[4][2];
            #pragma unroll
            for (int ni = 0; ni < 4; ni++) {
                const int r = (wn * 32 + ni * 8 + g) * LDA + kk + t * 2;
                bfh[ni][0] = *(const uint32_t*)&Bh[r];
                bfh[ni][1] = *(const uint32_t*)&Bh[r + 8];
                bfl[ni][0] = *(const uint32_t*)&Bl[r];
                bfl[ni][1] = *(const uint32_t*)&Bl[r + 8];
            }
            #pragma unroll
            for (int mi = 0; mi < 2; mi++)
                #pragma unroll
                for (int ni = 0; ni < 4; ni++) {
                    mma16816(acc[mi][ni], afh[mi], bfh[ni]);
                    mma16816(acc[mi][ni], afh[mi], bfl[ni]);
                    mma16816(acc[mi][ni], afl[mi], bfh[ni]);
                }
        }
        __syncthreads();
    }

    // ---- epilogue ----
    #pragma unroll
    for (int mi = 0; mi < 2; mi++) {
        const int row0 = m0 + wm * 32 + mi * 16 + g;
        #pragma unroll
        for (int ni = 0; ni < 4; ni++) {
            const int col = n0 + wn * 32 + ni * 8 + t * 2;
            float2 r01, r23;
            r01.x = acc[mi][ni][0]; r01.y = acc[mi][ni][1];
            r23.x = acc[mi][ni][2]; r23.y = acc[mi][ni][3];
            const size_t i0 = (size_t)row0 * N + col;
            const size_t i1 = (size_t)(row0 + 8) * N + col;
            if (EPI == 0) {
                float2 bv = *(const float2*)(extra + col);
                r01.x += bv.x; r01.y += bv.y;
                r23.x += bv.x; r23.y += bv.y;
            } else if (EPI == 2) {
                float2 e0 = *(const float2*)(extra + i0);
                float2 e1 = *(const float2*)(extra + i1);
                r01.x += e0.x; r01.y += e0.y;
                r23.x += e1.x; r23.y += e1.y;
            }
            *(float2*)(C + i0) = r01;
            *(float2*)(C + i1) = r23;
        }
    }
}

// ---------------- LayerNorm(x) * (1+scale) + shift -------------------------
__global__ void ln_film_kernel(const float* __restrict__ x,
                               const float* __restrict__ se,
                               float* __restrict__ h)
{
    const int m = blockIdx.x;
    const float* xr = x + (size_t)m * CC;
    const float* sc = se + (size_t)m * (2 * CC);
    float* hr = h + (size_t)m * CC;

    float v[4];
    float s = 0.f, s2 = 0.f;
    #pragma unroll
    for (int e = 0; e < 4; e++) {
        v[e] = xr[threadIdx.x + e * 256];
        s += v[e];
        s2 += v[e] * v[e];
    }
    __shared__ float shs[8], shs2[8], bcast[2];
    const int lane = threadIdx.x & 31, w = threadIdx.x >> 5;
    #pragma unroll
    for (int o = 16; o; o >>= 1) {
        s  += __shfl_xor_sync(0xffffffffu, s,  o);
        s2 += __shfl_xor_sync(0xffffffffu, s2, o);
    }
    if (lane == 0) { shs[w] = s; shs2[w] = s2; }
    __syncthreads();
    if (w == 0) {
        float a  = (lane < 8) ? shs[lane]  : 0.f;
        float a2 = (lane < 8) ? shs2[lane] : 0.f;
        #pragma unroll
        for (int o = 4; o; o >>= 1) {
            a  += __shfl_xor_sync(0xffffffffu, a,  o);
            a2 += __shfl_xor_sync(0xffffffffu, a2, o);
        }
        if (lane == 0) { bcast[0] = a; bcast[1] = a2; }
    }
    __syncthreads();
    const float mu  = bcast[0] * (1.f / CC);
    const float var = bcast[1] * (1.f / CC) - mu * mu;
    const float rs  = rsqrtf(var + EPSV);

    #pragma unroll
    for (int e = 0; e < 4; e++) {
        const int c = threadIdx.x + e * 256;
        hr[c] = (v[e] - mu) * rs * (1.f + sc[c]) + sc[c + CC];
    }
}

// ---------------- per-head LayerNorm of q and k (D=64 per segment) ---------
__global__ void qk_ln_kernel(float* __restrict__ qkv)
{
    const int seg  = blockIdx.x * 8 + (threadIdx.x >> 5);
    const int lane = threadIdx.x & 31;
    const int m = seg >> 5;
    const int r = seg & 31;
    float* base = qkv + (size_t)m * 3072 + (r >> 4) * 1024 + (r & 15) * 64;

    float a = base[lane];
    float b = base[lane + 32];
    float s = a + b, s2 = a * a + b * b;
    #pragma unroll
    for (int o = 16; o; o >>= 1) {
        s  += __shfl_xor_sync(0xffffffffu, s,  o);
        s2 += __shfl_xor_sync(0xffffffffu, s2, o);
    }
    const float mu  = s * (1.f / 64.f);
    const float var = s2 * (1.f / 64.f) - mu * mu;
    const float rs  = rsqrtf(var + EPSV);
    base[lane]      = (a - mu) * rs;
    base[lane + 32] = (b - mu) * rs;
}

// ---------------- flash attention (fp32, BM=BN=64, D=64) -------------------
__global__ void __launch_bounds__(256, 4)
flash_kernel(const float* __restrict__ qkv, float* __restrict__ o)
{
    constexpr int BMQ = 64, BNK = 64;
    __shared__ float Qs[BMQ * 64];
    __shared__ float KVs[BNK * 64];
    __shared__ float Ps[BMQ * 64];

    const int bh = blockIdx.y;
    const int b  = bh >> 4;
    const int h  = bh & 15;
    const int n0 = blockIdx.x * BMQ;

    const float* qb = qkv + (size_t)b * NN * 3072 + h * 64;
    const float* kb = qb + 1024;
    const float* vb = qb + 2048;

    const int tid = threadIdx.x;
    const int tx = tid & 15;
    const int ty = tid >> 4;

    for (int idx = tid; idx < BMQ * 64; idx += 256) {
        const int r = idx >> 6, c = idx & 63;
        Qs[r * 64 + c] = qb[(size_t)(n0 + r) * 3072 + c];
    }

    float acc[4][4];
    float mrow[4], lrow[4];
    #pragma unroll
    for (int i = 0; i < 4; i++) {
        mrow[i] = -1e30f; lrow[i] = 0.f;
        #pragma unroll
        for (int j = 0; j < 4; j++) acc[i][j] = 0.f;
    }

    const float sm = 0.125f;

    for (int kt = 0; kt < NN; kt += BNK) {
        __syncthreads();
        for (int idx = tid; idx < BNK * 64; idx += 256) {
            const int r = idx >> 6, c = idx & 63;
            KVs[r * 64 + (c ^ (r & 31))] = kb[(size_t)(kt + r) * 3072 + c];
        }
        __syncthreads();

        float s[4][4];
        #pragma unroll
        for (int i = 0; i < 4; i++)
            #pragma unroll
            for (int j = 0; j < 4; j++) s[i][j] = 0.f;

        #pragma unroll 8
        for (int kk = 0; kk < 64; kk++) {
            float ra[4], rb[4];
            #pragma unroll
            for (int i = 0; i < 4; i++) ra[i] = Qs[(ty * 4 + i) * 64 + kk];
            #pragma unroll
            for (int j = 0; j < 4; j++) {
                const int col = tx * 4 + j;
                rb[j] = KVs[col * 64 + (kk ^ (col & 31))];
            }
            #pragma unroll
            for (int i = 0; i < 4; i++)
                #pragma unroll
                for (int j = 0; j < 4; j++)
                    s[i][j] = fmaf(ra[i], rb[j], s[i][j]);
        }

        #pragma unroll
        for (int i = 0; i < 4; i++) {
            float mx = -1e30f;
            #pragma unroll
            for (int j = 0; j < 4; j++) { s[i][j] *= sm; mx = fmaxf(mx, s[i][j]); }
            #pragma unroll
            for (int o = 8; o; o >>= 1)
                mx = fmaxf(mx, __shfl_xor_sync(0xffffffffu, mx, o));
            const float mnew = fmaxf(mrow[i], mx);
            const float corr = __expf(mrow[i] - mnew);
            mrow[i] = mnew;
            lrow[i] *= corr;
            #pragma unroll
            for (int j = 0; j < 4; j++) acc[i][j] *= corr;
            float rsum = 0.f;
            #pragma unroll
            for (int j = 0; j < 4; j++) {
                const float p = __expf(s[i][j] - mnew);
                Ps[(ty * 4 + i) * 64 + tx * 4 + j] = p;
                rsum += p;
            }
            #pragma unroll
            for (int o = 8; o; o >>= 1)
                rsum += __shfl_xor_sync(0xffffffffu, rsum, o);
            lrow[i] += rsum;
        }
        __syncthreads();

        for (int idx = tid; idx < BNK * 64; idx += 256) {
            const int r = idx >> 6, c = idx & 63;
            KVs[r * 64 + (c ^ (r & 31))] = vb[(size_t)(kt + r) * 3072 + c];
        }
        __syncthreads();

        #pragma unroll 8
        for (int n = 0; n < 64; n++) {
            float rp[4], rv[4];
            #pragma unroll
            for (int i = 0; i < 4; i++) rp[i] = Ps[(ty * 4 + i) * 64 + n];
            #pragma unroll
            for (int j = 0; j < 4; j++) {
                const int col = tx * 4 + j;
                rv[j] = KVs[n * 64 + (col ^ (n & 31))];
            }
            #pragma unroll
            for (int i = 0; i < 4; i++)
                #pragma unroll
                for (int j = 0; j < 4; j++)
                    acc[i][j] = fmaf(rp[i], rv[j], acc[i][j]);
        }
    }

    #pragma unroll
    for (int i = 0; i < 4; i++) {
        const float inv = 1.f / lrow[i];
        const int row = n0 + ty * 4 + i;
        float* orow = o + (size_t)(b * NN + row) * CC + h * 64 + tx * 4;
        float4 r;
        r.x = acc[i][0] * inv; r.y = acc[i][1] * inv;
        r.z = acc[i][2] * inv; r.w = acc[i][3] * inv;
        *(float4*)orow = r;
    }
}

// ---------------- launcher -------------------------------------------------
extern "C" void kernel_launch(void* const* d_in, const int* in_sizes, int n_in,
                              void* d_out, int out_size)
{
    const float* x      = (const float*)d_in[0];
    const float* emb    = (const float*)d_in[1];
    const float* W_emb  = (const float*)d_in[2];
    const float* b_emb  = (const float*)d_in[3];
    const float* W_proj = (const float*)d_in[4];
    const float* W_out  = (const float*)d_in[5];
    float* out = (float*)d_out;

    float *se, *h, *qkv, *o;
    cudaGetSymbolAddress((void**)&se,  g_se);
    cudaGetSymbolAddress((void**)&h,   g_h);
    cudaGetSymbolAddress((void**)&qkv, g_qkv);
    cudaGetSymbolAddress((void**)&o,   g_o);

    // 1) se = emb @ W_emb^T + b_emb         (8192 x 2048 x 1024)
    bgemm_nt<0><<<dim3(2048 / 64, MM / 128), 256>>>(emb, W_emb, se, 2048, EMB, b_emb);
    // 2) h = LN(x)*(1+scale)+shift
    ln_film_kernel<<<MM, 256>>>(x, se, h);
    // 3) qkv = h @ W_proj^T                 (8192 x 3072 x 1024)
    bgemm_nt<1><<<dim3(3072 / 64, MM / 128), 256>>>(h, W_proj, qkv, 3072, CC, nullptr);
    // 4) per-head LN of q and k
    qk_ln_kernel<<<(MM * 32) / 8, 256>>>(qkv);
    // 5) flash attention -> o (B,N,C layout)
    flash_kernel<<<dim3(NN / 64, BB * HH), 256>>>(qkv, o);
    // 6) out = o + o @ W_out^T              (8192 x 1024 x 1024)
    bgemm_nt<2><<<dim3(1024 / 64, MM / 128), 256>>>(o, W_out, out, 1024, CC, o);
}

// round 4
// speedup vs baseline: 3.8219x; 2.4363x over previous
#include <cuda_runtime.h>
#include <cuda_bf16.h>
#include <cstdint>

// Problem constants
#define BB 4
#define NN 2048
#define CC 1024
#define HH 16
#define DD 64
#define MM (BB*NN)          // 8192 token rows
#define EMB 1024
#define EPSV 1e-5f

// ---------------- scratch (device globals; no allocation allowed) ----------
__device__ float g_se[(size_t)MM * 2048];   // 64 MB
__device__ float g_h [(size_t)MM * 1024];   // 32 MB
__device__ float g_qkv[(size_t)MM * 3072];  // 96 MB
__device__ float g_o [(size_t)MM * 1024];   // 32 MB

// ---------------- common mma ----------------------------------------------
__device__ __forceinline__ void mma16816(float* c, const uint32_t* a, const uint32_t* b)
{
    asm volatile(
        "mma.sync.aligned.m16n8k16.row.col.f32.bf16.bf16.f32 "
        "{%0,%1,%2,%3}, {%4,%5,%6,%7}, {%8,%9}, {%0,%1,%2,%3};\n"
        : "+f"(c[0]), "+f"(c[1]), "+f"(c[2]), "+f"(c[3])
        : "r"(a[0]), "r"(a[1]), "r"(a[2]), "r"(a[3]), "r"(b[0]), "r"(b[1]));
}

__device__ __forceinline__ float ex2f(float x)
{
    float r;
    asm("ex2.approx.f32 %0, %1;" : "=f"(r) : "f"(x));
    return r;
}

// ---------------- bf16x3 tensor-core GEMM: C = A(MxK) * B(NxK)^T ----------
#define LDA 40  // padded row stride (bf16): 80B = 20 banks -> conflict-free frags

template<int EPI>
__global__ void __launch_bounds__(256, 2)
bgemm_nt(const float* __restrict__ A, const float* __restrict__ B,
         float* __restrict__ C, int N, int K, const float* __restrict__ extra)
{
    __shared__ __nv_bfloat16 Ah[128 * LDA], Al[128 * LDA];
    __shared__ __nv_bfloat16 Bh[64 * LDA],  Bl[64 * LDA];

    const int tid  = threadIdx.x;
    const int lane = tid & 31;
    const int wid  = tid >> 5;
    const int g    = lane >> 2;
    const int t    = lane & 3;
    const int wm   = wid >> 1;
    const int wn   = wid & 1;

    const int m0 = blockIdx.y * 128;
    const int n0 = blockIdx.x * 64;

    const int lr = tid >> 3;
    const int lc = (tid & 7) * 4;

    float acc[2][4][4];
    #pragma unroll
    for (int mi = 0; mi < 2; mi++)
        #pragma unroll
        for (int ni = 0; ni < 4; ni++)
            #pragma unroll
            for (int e = 0; e < 4; e++) acc[mi][ni][e] = 0.f;

    for (int k0 = 0; k0 < K; k0 += 32) {
        #pragma unroll
        for (int i = 0; i < 4; i++) {
            const int r = lr + 32 * i;
            float4 v = *(const float4*)(A + (size_t)(m0 + r) * K + k0 + lc);
            __nv_bfloat16 hx = __float2bfloat16_rn(v.x);
            __nv_bfloat16 hy = __float2bfloat16_rn(v.y);
            __nv_bfloat16 hz = __float2bfloat16_rn(v.z);
            __nv_bfloat16 hw = __float2bfloat16_rn(v.w);
            __nv_bfloat162 h01; h01.x = hx; h01.y = hy;
            __nv_bfloat162 h23; h23.x = hz; h23.y = hw;
            __nv_bfloat162 l01, l23;
            l01.x = __float2bfloat16_rn(v.x - __bfloat162float(hx));
            l01.y = __float2bfloat16_rn(v.y - __bfloat162float(hy));
            l23.x = __float2bfloat16_rn(v.z - __bfloat162float(hz));
            l23.y = __float2bfloat16_rn(v.w - __bfloat162float(hw));
            *(__nv_bfloat162*)&Ah[r * LDA + lc]     = h01;
            *(__nv_bfloat162*)&Ah[r * LDA + lc + 2] = h23;
            *(__nv_bfloat162*)&Al[r * LDA + lc]     = l01;
            *(__nv_bfloat162*)&Al[r * LDA + lc + 2] = l23;
        }
        #pragma unroll
        for (int i = 0; i < 2; i++) {
            const int r = lr + 32 * i;
            float4 v = *(const float4*)(B + (size_t)(n0 + r) * K + k0 + lc);
            __nv_bfloat16 hx = __float2bfloat16_rn(v.x);
            __nv_bfloat16 hy = __float2bfloat16_rn(v.y);
            __nv_bfloat16 hz = __float2bfloat16_rn(v.z);
            __nv_bfloat16 hw = __float2bfloat16_rn(v.w);
            __nv_bfloat162 h01; h01.x = hx; h01.y = hy;
            __nv_bfloat162 h23; h23.x = hz; h23.y = hw;
            __nv_bfloat162 l01, l23;
            l01.x = __float2bfloat16_rn(v.x - __bfloat162float(hx));
            l01.y = __float2bfloat16_rn(v.y - __bfloat162float(hy));
            l23.x = __float2bfloat16_rn(v.z - __bfloat162float(hz));
            l23.y = __float2bfloat16_rn(v.w - __bfloat162float(hw));
            *(__nv_bfloat162*)&Bh[r * LDA + lc]     = h01;
            *(__nv_bfloat162*)&Bh[r * LDA + lc + 2] = h23;
            *(__nv_bfloat162*)&Bl[r * LDA + lc]     = l01;
            *(__nv_bfloat162*)&Bl[r * LDA + lc + 2] = l23;
        }
        __syncthreads();

        #pragma unroll
        for (int kk = 0; kk < 32; kk += 16) {
            uint32_t afh[2][4], afl[2][4];
            #pragma unroll
            for (int mi = 0; mi < 2; mi++) {
                const int r0 = (wm * 32 + mi * 16 + g) * LDA + kk + t * 2;
                const int r1 = r0 + 8 * LDA;
                afh[mi][0] = *(const uint32_t*)&Ah[r0];
                afh[mi][1] = *(const uint32_t*)&Ah[r1];
                afh[mi][2] = *(const uint32_t*)&Ah[r0 + 8];
                afh[mi][3] = *(const uint32_t*)&Ah[r1 + 8];
                afl[mi][0] = *(const uint32_t*)&Al[r0];
                afl[mi][1] = *(const uint32_t*)&Al[r1];
                afl[mi][2] = *(const uint32_t*)&Al[r0 + 8];
                afl[mi][3] = *(const uint32_t*)&Al[r1 + 8];
            }
            uint32_t bfh[4][2], bfl[4][2];
            #pragma unroll
            for (int ni = 0; ni < 4; ni++) {
                const int r = (wn * 32 + ni * 8 + g) * LDA + kk + t * 2;
                bfh[ni][0] = *(const uint32_t*)&Bh[r];
                bfh[ni][1] = *(const uint32_t*)&Bh[r + 8];
                bfl[ni][0] = *(const uint32_t*)&Bl[r];
                bfl[ni][1] = *(const uint32_t*)&Bl[r + 8];
            }
            #pragma unroll
            for (int mi = 0; mi < 2; mi++)
                #pragma unroll
                for (int ni = 0; ni < 4; ni++) {
                    mma16816(acc[mi][ni], afh[mi], bfh[ni]);
                    mma16816(acc[mi][ni], afh[mi], bfl[ni]);
                    mma16816(acc[mi][ni], afl[mi], bfh[ni]);
                }
        }
        __syncthreads();
    }

    #pragma unroll
    for (int mi = 0; mi < 2; mi++) {
        const int row0 = m0 + wm * 32 + mi * 16 + g;
        #pragma unroll
        for (int ni = 0; ni < 4; ni++) {
            const int col = n0 + wn * 32 + ni * 8 + t * 2;
            float2 r01, r23;
            r01.x = acc[mi][ni][0]; r01.y = acc[mi][ni][1];
            r23.x = acc[mi][ni][2]; r23.y = acc[mi][ni][3];
            const size_t i0 = (size_t)row0 * N + col;
            const size_t i1 = (size_t)(row0 + 8) * N + col;
            if (EPI == 0) {
                float2 bv = *(const float2*)(extra + col);
                r01.x += bv.x; r01.y += bv.y;
                r23.x += bv.x; r23.y += bv.y;
            } else if (EPI == 2) {
                float2 e0 = *(const float2*)(extra + i0);
                float2 e1 = *(const float2*)(extra + i1);
                r01.x += e0.x; r01.y += e0.y;
                r23.x += e1.x; r23.y += e1.y;
            }
            *(float2*)(C + i0) = r01;
            *(float2*)(C + i1) = r23;
        }
    }
}

// ---------------- LayerNorm(x) * (1+scale) + shift -------------------------
__global__ void ln_film_kernel(const float* __restrict__ x,
                               const float* __restrict__ se,
                               float* __restrict__ h)
{
    const int m = blockIdx.x;
    const float* xr = x + (size_t)m * CC;
    const float* sc = se + (size_t)m * (2 * CC);
    float* hr = h + (size_t)m * CC;

    float v[4];
    float s = 0.f, s2 = 0.f;
    #pragma unroll
    for (int e = 0; e < 4; e++) {
        v[e] = xr[threadIdx.x + e * 256];
        s += v[e];
        s2 += v[e] * v[e];
    }
    __shared__ float shs[8], shs2[8], bcast[2];
    const int lane = threadIdx.x & 31, w = threadIdx.x >> 5;
    #pragma unroll
    for (int o = 16; o; o >>= 1) {
        s  += __shfl_xor_sync(0xffffffffu, s,  o);
        s2 += __shfl_xor_sync(0xffffffffu, s2, o);
    }
    if (lane == 0) { shs[w] = s; shs2[w] = s2; }
    __syncthreads();
    if (w == 0) {
        float a  = (lane < 8) ? shs[lane]  : 0.f;
        float a2 = (lane < 8) ? shs2[lane] : 0.f;
        #pragma unroll
        for (int o = 4; o; o >>= 1) {
            a  += __shfl_xor_sync(0xffffffffu, a,  o);
            a2 += __shfl_xor_sync(0xffffffffu, a2, o);
        }
        if (lane == 0) { bcast[0] = a; bcast[1] = a2; }
    }
    __syncthreads();
    const float mu  = bcast[0] * (1.f / CC);
    const float var = bcast[1] * (1.f / CC) - mu * mu;
    const float rs  = rsqrtf(var + EPSV);

    #pragma unroll
    for (int e = 0; e < 4; e++) {
        const int c = threadIdx.x + e * 256;
        hr[c] = (v[e] - mu) * rs * (1.f + sc[c]) + sc[c + CC];
    }
}

// ---------------- per-head LayerNorm of q and k ----------------------------
__global__ void qk_ln_kernel(float* __restrict__ qkv)
{
    const int seg  = blockIdx.x * 8 + (threadIdx.x >> 5);
    const int lane = threadIdx.x & 31;
    const int m = seg >> 5;
    const int r = seg & 31;
    float* base = qkv + (size_t)m * 3072 + (r >> 4) * 1024 + (r & 15) * 64;

    float a = base[lane];
    float b = base[lane + 32];
    float s = a + b, s2 = a * a + b * b;
    #pragma unroll
    for (int o = 16; o; o >>= 1) {
        s  += __shfl_xor_sync(0xffffffffu, s,  o);
        s2 += __shfl_xor_sync(0xffffffffu, s2, o);
    }
    const float mu  = s * (1.f / 64.f);
    const float var = s2 * (1.f / 64.f) - mu * mu;
    const float rs  = rsqrtf(var + EPSV);
    base[lane]      = (a - mu) * rs;
    base[lane + 32] = (b - mu) * rs;
}

// ---------------- flash attention (tensor-core, bf16x3) --------------------
// BM=128 (8 warps x 16 rows), BN=64, D=64. P kept in registers for PV mma.
#define FLD 72  // padded stride (bf16): 144B = 36 banks; frag banks (4g+t)%32 distinct

// dynamic smem layout (bf16 elems):
#define QH_OFF 0
#define QL_OFF (128 * FLD)
#define KH_OFF (2 * 128 * FLD)
#define KL_OFF (KH_OFF + 64 * FLD)
#define VH_OFF (KL_OFF + 64 * FLD)
#define VL_OFF (VH_OFF + 64 * FLD)
#define FL_SMEM_BYTES ((VL_OFF + 64 * FLD) * 2)

__global__ void __launch_bounds__(256, 2)
flash_mma_kernel(const float* __restrict__ qkv, float* __restrict__ o)
{
    extern __shared__ __nv_bfloat16 sm[];
    __nv_bfloat16* Qh = sm + QH_OFF;
    __nv_bfloat16* Ql = sm + QL_OFF;
    __nv_bfloat16* Kh = sm + KH_OFF;
    __nv_bfloat16* Kl = sm + KL_OFF;
    __nv_bfloat16* Vh = sm + VH_OFF;   // transposed: Vh[d][pos]
    __nv_bfloat16* Vl = sm + VL_OFF;

    const int tid  = threadIdx.x;
    const int lane = tid & 31;
    const int wid  = tid >> 5;
    const int g    = lane >> 2;
    const int t    = lane & 3;

    const int b  = blockIdx.y >> 4;
    const int h  = blockIdx.y & 15;
    const int n0 = blockIdx.x * 128;

    const float* qb = qkv + (size_t)b * NN * 3072 + h * 64;
    const float* kb = qb + 1024;
    const float* vb = qb + 2048;

    // ---- load Q tile (128x64), split hi/lo ----
    {
        const int lr = tid >> 1;
        const int c0 = (tid & 1) * 32;
        #pragma unroll
        for (int i = 0; i < 8; i++) {
            const int c = c0 + i * 4;
            float4 v = *(const float4*)(qb + (size_t)(n0 + lr) * 3072 + c);
            __nv_bfloat16 hx = __float2bfloat16_rn(v.x);
            __nv_bfloat16 hy = __float2bfloat16_rn(v.y);
            __nv_bfloat16 hz = __float2bfloat16_rn(v.z);
            __nv_bfloat16 hw = __float2bfloat16_rn(v.w);
            __nv_bfloat162 h01; h01.x = hx; h01.y = hy;
            __nv_bfloat162 h23; h23.x = hz; h23.y = hw;
            __nv_bfloat162 l01, l23;
            l01.x = __float2bfloat16_rn(v.x - __bfloat162float(hx));
            l01.y = __float2bfloat16_rn(v.y - __bfloat162float(hy));
            l23.x = __float2bfloat16_rn(v.z - __bfloat162float(hz));
            l23.y = __float2bfloat16_rn(v.w - __bfloat162float(hw));
            *(__nv_bfloat162*)&Qh[lr * FLD + c]     = h01;
            *(__nv_bfloat162*)&Qh[lr * FLD + c + 2] = h23;
            *(__nv_bfloat162*)&Ql[lr * FLD + c]     = l01;
            *(__nv_bfloat162*)&Ql[lr * FLD + c + 2] = l23;
        }
    }

    float oacc[8][4];
    #pragma unroll
    for (int nb = 0; nb < 8; nb++)
        #pragma unroll
        for (int e = 0; e < 4; e++) oacc[nb][e] = 0.f;
    float m0r = -1e30f, m1r = -1e30f, l0r = 0.f, l1r = 0.f;

    const float scl = 0.125f * 1.44269504088896f;  // 1/sqrt(D) * log2(e)

    for (int kt = 0; kt < NN; kt += 64) {
        __syncthreads();
        // ---- load K tile (64x64) + V tile transposed ----
        {
            const int lr = tid >> 2;
            const int c0 = (tid & 3) * 16;
            #pragma unroll
            for (int i = 0; i < 4; i++) {
                const int c = c0 + i * 4;
                float4 v = *(const float4*)(kb + (size_t)(kt + lr) * 3072 + c);
                __nv_bfloat16 hx = __float2bfloat16_rn(v.x);
                __nv_bfloat16 hy = __float2bfloat16_rn(v.y);
                __nv_bfloat16 hz = __float2bfloat16_rn(v.z);
                __nv_bfloat16 hw = __float2bfloat16_rn(v.w);
                __nv_bfloat162 h01; h01.x = hx; h01.y = hy;
                __nv_bfloat162 h23; h23.x = hz; h23.y = hw;
                __nv_bfloat162 l01, l23;
                l01.x = __float2bfloat16_rn(v.x - __bfloat162float(hx));
                l01.y = __float2bfloat16_rn(v.y - __bfloat162float(hy));
                l23.x = __float2bfloat16_rn(v.z - __bfloat162float(hz));
                l23.y = __float2bfloat16_rn(v.w - __bfloat162float(hw));
                *(__nv_bfloat162*)&Kh[lr * FLD + c]     = h01;
                *(__nv_bfloat162*)&Kh[lr * FLD + c + 2] = h23;
                *(__nv_bfloat162*)&Kl[lr * FLD + c]     = l01;
                *(__nv_bfloat162*)&Kl[lr * FLD + c + 2] = l23;
            }
            #pragma unroll
            for (int i = 0; i < 4; i++) {
                const int c = c0 + i * 4;
                float4 v = *(const float4*)(vb + (size_t)(kt + lr) * 3072 + c);
                float vv[4] = {v.x, v.y, v.z, v.w};
                #pragma unroll
                for (int j = 0; j < 4; j++) {
                    __nv_bfloat16 hi = __float2bfloat16_rn(vv[j]);
                    Vh[(c + j) * FLD + lr] = hi;
                    Vl[(c + j) * FLD + lr] = __float2bfloat16_rn(vv[j] - __bfloat162float(hi));
                }
            }
        }
        __syncthreads();

        // ---- S = Q K^T (bf16x3) ----
        float sacc[8][4];
        #pragma unroll
        for (int nb = 0; nb < 8; nb++)
            #pragma unroll
            for (int e = 0; e < 4; e++) sacc[nb][e] = 0.f;

        #pragma unroll
        for (int kk = 0; kk < 4; kk++) {
            uint32_t ah[4], al[4];
            const int ab = (wid * 16 + g) * FLD + kk * 16 + t * 2;
            ah[0] = *(const uint32_t*)&Qh[ab];
            ah[1] = *(const uint32_t*)&Qh[ab + 8 * FLD];
            ah[2] = *(const uint32_t*)&Qh[ab + 8];
            ah[3] = *(const uint32_t*)&Qh[ab + 8 * FLD + 8];
            al[0] = *(const uint32_t*)&Ql[ab];
            al[1] = *(const uint32_t*)&Ql[ab + 8 * FLD];
            al[2] = *(const uint32_t*)&Ql[ab + 8];
            al[3] = *(const uint32_t*)&Ql[ab + 8 * FLD + 8];
            #pragma unroll
            for (int nb = 0; nb < 8; nb++) {
                uint32_t bh[2], bl[2];
                const int bbse = (nb * 8 + g) * FLD + kk * 16 + t * 2;
                bh[0] = *(const uint32_t*)&Kh[bbse];
                bh[1] = *(const uint32_t*)&Kh[bbse + 8];
                bl[0] = *(const uint32_t*)&Kl[bbse];
                bl[1] = *(const uint32_t*)&Kl[bbse + 8];
                mma16816(sacc[nb], ah, bh);
                mma16816(sacc[nb], ah, bl);
                mma16816(sacc[nb], al, bh);
            }
        }

        // ---- online softmax (rows g and g+8 within warp tile) ----
        float mx0 = -1e30f, mx1 = -1e30f;
        #pragma unroll
        for (int nb = 0; nb < 8; nb++) {
            sacc[nb][0] *= scl; sacc[nb][1] *= scl;
            sacc[nb][2] *= scl; sacc[nb][3] *= scl;
            mx0 = fmaxf(mx0, fmaxf(sacc[nb][0], sacc[nb][1]));
            mx1 = fmaxf(mx1, fmaxf(sacc[nb][2], sacc[nb][3]));
        }
        mx0 = fmaxf(mx0, __shfl_xor_sync(0xffffffffu, mx0, 1));
        mx0 = fmaxf(mx0, __shfl_xor_sync(0xffffffffu, mx0, 2));
        mx1 = fmaxf(mx1, __shfl_xor_sync(0xffffffffu, mx1, 1));
        mx1 = fmaxf(mx1, __shfl_xor_sync(0xffffffffu, mx1, 2));
        const float mn0 = fmaxf(m0r, mx0);
        const float mn1 = fmaxf(m1r, mx1);
        const float co0 = ex2f(m0r - mn0);
        const float co1 = ex2f(m1r - mn1);
        m0r = mn0; m1r = mn1;
        l0r *= co0; l1r *= co1;
        #pragma unroll
        for (int nb = 0; nb < 8; nb++) {
            oacc[nb][0] *= co0; oacc[nb][1] *= co0;
            oacc[nb][2] *= co1; oacc[nb][3] *= co1;
        }
        float rs0 = 0.f, rs1 = 0.f;
        #pragma unroll
        for (int nb = 0; nb < 8; nb++) {
            sacc[nb][0] = ex2f(sacc[nb][0] - mn0);
            sacc[nb][1] = ex2f(sacc[nb][1] - mn0);
            sacc[nb][2] = ex2f(sacc[nb][2] - mn1);
            sacc[nb][3] = ex2f(sacc[nb][3] - mn1);
            rs0 += sacc[nb][0] + sacc[nb][1];
            rs1 += sacc[nb][2] + sacc[nb][3];
        }
        rs0 += __shfl_xor_sync(0xffffffffu, rs0, 1);
        rs0 += __shfl_xor_sync(0xffffffffu, rs0, 2);
        rs1 += __shfl_xor_sync(0xffffffffu, rs1, 1);
        rs1 += __shfl_xor_sync(0xffffffffu, rs1, 2);
        l0r += rs0; l1r += rs1;

        // ---- O += P V (P in registers, bf16x3) ----
        #pragma unroll
        for (int kbk = 0; kbk < 4; kbk++) {
            uint32_t pah[4], pal[4];
            #pragma unroll
            for (int half = 0; half < 2; half++) {
                const float p0 = sacc[2 * kbk + half][0];
                const float p1 = sacc[2 * kbk + half][1];
                const float p2 = sacc[2 * kbk + half][2];
                const float p3 = sacc[2 * kbk + half][3];
                __nv_bfloat162 hA; hA.x = __float2bfloat16_rn(p0); hA.y = __float2bfloat16_rn(p1);
                __nv_bfloat162 hB; hB.x = __float2bfloat16_rn(p2); hB.y = __float2bfloat16_rn(p3);
                __nv_bfloat162 lA, lB;
                lA.x = __float2bfloat16_rn(p0 - __bfloat162float(hA.x));
                lA.y = __float2bfloat16_rn(p1 - __bfloat162float(hA.y));
                lB.x = __float2bfloat16_rn(p2 - __bfloat162float(hB.x));
                lB.y = __float2bfloat16_rn(p3 - __bfloat162float(hB.y));
                pah[0 + 2 * half] = *(const uint32_t*)&hA;   // rows g,   k-cols lo/hi half
                pah[1 + 2 * half] = *(const uint32_t*)&hB;   // rows g+8
                pal[0 + 2 * half] = *(const uint32_t*)&lA;
                pal[1 + 2 * half] = *(const uint32_t*)&lB;
            }
            #pragma unroll
            for (int nb = 0; nb < 8; nb++) {
                uint32_t vh[2], vl[2];
                const int vbse = (nb * 8 + g) * FLD + kbk * 16 + t * 2;
                vh[0] = *(const uint32_t*)&Vh[vbse];
                vh[1] = *(const uint32_t*)&Vh[vbse + 8];
                vl[0] = *(const uint32_t*)&Vl[vbse];
                vl[1] = *(const uint32_t*)&Vl[vbse + 8];
                mma16816(oacc[nb], pah, vh);
                mma16816(oacc[nb], pah, vl);
                mma16816(oacc[nb], pal, vh);
            }
        }
    }

    // ---- epilogue ----
    const float inv0 = 1.f / l0r;
    const float inv1 = 1.f / l1r;
    const int row0 = n0 + wid * 16 + g;
    const int row1 = row0 + 8;
    float* ob = o + (size_t)b * NN * CC + h * 64;
    #pragma unroll
    for (int nb = 0; nb < 8; nb++) {
        const int col = nb * 8 + t * 2;
        float2 r0, r1;
        r0.x = oacc[nb][0] * inv0; r0.y = oacc[nb][1] * inv0;
        r1.x = oacc[nb][2] * inv1; r1.y = oacc[nb][3] * inv1;
        *(float2*)(ob + (size_t)row0 * CC + col) = r0;
        *(float2*)(ob + (size_t)row1 * CC + col) = r1;
    }
}

// ---------------- launcher -------------------------------------------------
extern "C" void kernel_launch(void* const* d_in, const int* in_sizes, int n_in,
                              void* d_out, int out_size)
{
    const float* x      = (const float*)d_in[0];
    const float* emb    = (const float*)d_in[1];
    const float* W_emb  = (const float*)d_in[2];
    const float* b_emb  = (const float*)d_in[3];
    const float* W_proj = (const float*)d_in[4];
    const float* W_out  = (const float*)d_in[5];
    float* out = (float*)d_out;

    float *se, *h, *qkv, *o;
    cudaGetSymbolAddress((void**)&se,  g_se);
    cudaGetSymbolAddress((void**)&h,   g_h);
    cudaGetSymbolAddress((void**)&qkv, g_qkv);
    cudaGetSymbolAddress((void**)&o,   g_o);

    static int smem_set = 0;
    if (!smem_set) {
        cudaFuncSetAttribute(flash_mma_kernel,
                             cudaFuncAttributeMaxDynamicSharedMemorySize,
                             FL_SMEM_BYTES);
        smem_set = 1;
    }

    // 1) se = emb @ W_emb^T + b_emb
    bgemm_nt<0><<<dim3(2048 / 64, MM / 128), 256>>>(emb, W_emb, se, 2048, EMB, b_emb);
    // 2) h = LN(x)*(1+scale)+shift
    ln_film_kernel<<<MM, 256>>>(x, se, h);
    // 3) qkv = h @ W_proj^T
    bgemm_nt<1><<<dim3(3072 / 64, MM / 128), 256>>>(h, W_proj, qkv, 3072, CC, nullptr);
    // 4) per-head LN of q and k
    qk_ln_kernel<<<(MM * 32) / 8, 256>>>(qkv);
    // 5) flash attention (tensor core) -> o (B,N,C layout)
    flash_mma_kernel<<<dim3(NN / 128, BB * HH), 256, FL_SMEM_BYTES>>>(qkv, o);
    // 6) out = o + o @ W_out^T
    bgemm_nt<2><<<dim3(1024 / 64, MM / 128), 256>>>(o, W_out, out, 1024, CC, o);
}

// round 6
// speedup vs baseline: 3.8844x; 1.0164x over previous
#include <cuda_runtime.h>
#include <cuda_bf16.h>
#include <cstdint>

// Problem constants
#define BB 4
#define NN 2048
#define CC 1024
#define HH 16
#define DD 64
#define MM (BB*NN)          // 8192 token rows
#define EMB 1024
#define EPSV 1e-5f

// ---------------- scratch (device globals; no allocation allowed) ----------
__device__ float g_se [(size_t)MM * 2048];              // 64 MB
__device__ float g_qkv[(size_t)MM * 3072];              // 96 MB
__device__ float g_o  [(size_t)MM * 1024];              // 32 MB
__device__ __nv_bfloat16 g_embh[(size_t)MM * 1024], g_embl[(size_t)MM * 1024];
__device__ __nv_bfloat16 g_hh  [(size_t)MM * 1024], g_hl  [(size_t)MM * 1024];
__device__ __nv_bfloat16 g_qkvh[(size_t)MM * 3072], g_qkvl[(size_t)MM * 3072];
__device__ __nv_bfloat16 g_oh  [(size_t)MM * 1024], g_ol  [(size_t)MM * 1024];
__device__ __nv_bfloat16 g_Wembh[2048 * 1024], g_Wembl[2048 * 1024];
__device__ __nv_bfloat16 g_Wprjh[3072 * 1024], g_Wprjl[3072 * 1024];
__device__ __nv_bfloat16 g_Wouth[1024 * 1024], g_Woutl[1024 * 1024];

// ---------------- helpers --------------------------------------------------
__device__ __forceinline__ void mma16816(float* c, const uint32_t* a, const uint32_t* b)
{
    asm volatile(
        "mma.sync.aligned.m16n8k16.row.col.f32.bf16.bf16.f32 "
        "{%0,%1,%2,%3}, {%4,%5,%6,%7}, {%8,%9}, {%0,%1,%2,%3};\n"
        : "+f"(c[0]), "+f"(c[1]), "+f"(c[2]), "+f"(c[3])
        : "r"(a[0]), "r"(a[1]), "r"(a[2]), "r"(a[3]), "r"(b[0]), "r"(b[1]));
}

__device__ __forceinline__ float ex2f(float x)
{
    float r;
    asm("ex2.approx.f32 %0, %1;" : "=f"(r) : "f"(x));
    return r;
}

__device__ __forceinline__ void split1(float v, __nv_bfloat16& h, __nv_bfloat16& l)
{
    h = __float2bfloat16_rn(v);
    l = __float2bfloat16_rn(v - __bfloat162float(h));
}

__device__ __forceinline__ void cp_async16(void* s, const void* g)
{
    uint32_t sa = (uint32_t)__cvta_generic_to_shared(s);
    asm volatile("cp.async.cg.shared.global [%0], [%1], 16;\n" :: "r"(sa), "l"(g));
}

// ---------------- split pass: fp32 -> bf16 hi/lo ---------------------------
__global__ void split_kernel(const float4* __restrict__ src,
                             uint2* __restrict__ hi, uint2* __restrict__ lo, int n4)
{
    const int i = blockIdx.x * 256 + threadIdx.x;
    if (i >= n4) return;
    float4 v = src[i];
    __nv_bfloat162 h01, h23, l01, l23;
    split1(v.x, h01.x, l01.x);
    split1(v.y, h01.y, l01.y);
    split1(v.z, h23.x, l23.x);
    split1(v.w, h23.y, l23.y);
    uint2 ho, loo;
    ho.x  = *(const uint32_t*)&h01; ho.y  = *(const uint32_t*)&h23;
    loo.x = *(const uint32_t*)&l01; loo.y = *(const uint32_t*)&l23;
    hi[i] = ho; lo[i] = loo;
}

// ---------------- bf16x3 GEMM, bf16 hi/lo inputs, cp.async 2-stage ---------
// C(fp32) = A(MxK) * B(NxK)^T ; EPI 0: +bias[n], 1: none, 2: +extra[m*N+n]
#define LDA 40                // padded row stride (bf16): 80B = 20 banks
#define STG_ELEMS 15360       // per-stage smem elems (Ah 5120 | Al 5120 | Bh 2560 | Bl 2560)
#define GEMM_SMEM_BYTES (2 * STG_ELEMS * 2)

template<int EPI>
__global__ void __launch_bounds__(256, 2)
bgemm_bb(const __nv_bfloat16* __restrict__ Ah_g, const __nv_bfloat16* __restrict__ Al_g,
         const __nv_bfloat16* __restrict__ Bh_g, const __nv_bfloat16* __restrict__ Bl_g,
         float* __restrict__ C, int N, int K, const float* __restrict__ extra)
{
    extern __shared__ __nv_bfloat16 smem[];

    const int tid  = threadIdx.x;
    const int lane = tid & 31;
    const int wid  = tid >> 5;
    const int g    = lane >> 2;
    const int t    = lane & 3;
    const int wm   = wid >> 1;
    const int wn   = wid & 1;

    const int m0 = blockIdx.y * 128;
    const int n0 = blockIdx.x * 64;

    float acc[2][4][4];
    #pragma unroll
    for (int mi = 0; mi < 2; mi++)
        #pragma unroll
        for (int ni = 0; ni < 4; ni++)
            #pragma unroll
            for (int e = 0; e < 4; e++) acc[mi][ni][e] = 0.f;

    // loader jobs
    const int arow = tid >> 2;            // 0..63 (A uses arow and arow+64)
    const int ach  = (tid & 3) * 8;       // elem chunk 0,8,16,24

    auto issue_stage = [&](int st, int k0) {
        __nv_bfloat16* sa_h = smem + st * STG_ELEMS;
        __nv_bfloat16* sa_l = sa_h + 5120;
        __nv_bfloat16* sb_h = sa_h + 10240;
        __nv_bfloat16* sb_l = sa_h + 12800;
        #pragma unroll
        for (int rep = 0; rep < 2; rep++) {
            const int row = arow + rep * 64;
            const size_t goff = (size_t)(m0 + row) * K + k0 + ach;
            cp_async16(&sa_h[row * LDA + ach], Ah_g + goff);
            cp_async16(&sa_l[row * LDA + ach], Al_g + goff);
        }
        {
            const size_t goff = (size_t)(n0 + arow) * K + k0 + ach;
            cp_async16(&sb_h[arow * LDA + ach], Bh_g + goff);
            cp_async16(&sb_l[arow * LDA + ach], Bl_g + goff);
        }
        asm volatile("cp.async.commit_group;\n");
    };

    const int KT = K >> 5;
    issue_stage(0, 0);

    for (int kt = 0; kt < KT; kt++) {
        if (kt + 1 < KT) {
            issue_stage((kt + 1) & 1, (kt + 1) << 5);
            asm volatile("cp.async.wait_group 1;\n");
        } else {
            asm volatile("cp.async.wait_group 0;\n");
        }
        __syncthreads();

        const __nv_bfloat16* Ah = smem + (kt & 1) * STG_ELEMS;
        const __nv_bfloat16* Al = Ah + 5120;
        const __nv_bfloat16* Bh = Ah + 10240;
        const __nv_bfloat16* Bl = Ah + 12800;

        #pragma unroll
        for (int kk = 0; kk < 32; kk += 16) {
            uint32_t afh[2][4], afl[2][4];
            #pragma unroll
            for (int mi = 0; mi < 2; mi++) {
                const int r0 = (wm * 32 + mi * 16 + g) * LDA + kk + t * 2;
                const int r1 = r0 + 8 * LDA;
                afh[mi][0] = *(const uint32_t*)&Ah[r0];
                afh[mi][1] = *(const uint32_t*)&Ah[r1];
                afh[mi][2] = *(const uint32_t*)&Ah[r0 + 8];
                afh[mi][3] = *(const uint32_t*)&Ah[r1 + 8];
                afl[mi][0] = *(const uint32_t*)&Al[r0];
                afl[mi][1] = *(const uint32_t*)&Al[r1];
                afl[mi][2] = *(const uint32_t*)&Al[r0 + 8];
                afl[mi][3] = *(const uint32_t*)&Al[r1 + 8];
            }
            uint32_t bfh[4][2], bfl[4][2];
            #pragma unroll
            for (int ni = 0; ni < 4; ni++) {
                const int r = (wn * 32 + ni * 8 + g) * LDA + kk + t * 2;
                bfh[ni][0] = *(const uint32_t*)&Bh[r];
                bfh[ni][1] = *(const uint32_t*)&Bh[r + 8];
                bfl[ni][0] = *(const uint32_t*)&Bl[r];
                bfl[ni][1] = *(const uint32_t*)&Bl[r + 8];
            }
            #pragma unroll
            for (int mi = 0; mi < 2; mi++)
                #pragma unroll
                for (int ni = 0; ni < 4; ni++) {
                    mma16816(acc[mi][ni], afh[mi], bfh[ni]);
                    mma16816(acc[mi][ni], afh[mi], bfl[ni]);
                    mma16816(acc[mi][ni], afl[mi], bfh[ni]);
                }
        }
        __syncthreads();
    }

    #pragma unroll
    for (int mi = 0; mi < 2; mi++) {
        const int row0 = m0 + wm * 32 + mi * 16 + g;
        #pragma unroll
        for (int ni = 0; ni < 4; ni++) {
            const int col = n0 + wn * 32 + ni * 8 + t * 2;
            float2 r01, r23;
            r01.x = acc[mi][ni][0]; r01.y = acc[mi][ni][1];
            r23.x = acc[mi][ni][2]; r23.y = acc[mi][ni][3];
            const size_t i0 = (size_t)row0 * N + col;
            const size_t i1 = (size_t)(row0 + 8) * N + col;
            if (EPI == 0) {
                float2 bv = *(const float2*)(extra + col);
                r01.x += bv.x; r01.y += bv.y;
                r23.x += bv.x; r23.y += bv.y;
            } else if (EPI == 2) {
                float2 e0 = *(const float2*)(extra + i0);
                float2 e1 = *(const float2*)(extra + i1);
                r01.x += e0.x; r01.y += e0.y;
                r23.x += e1.x; r23.y += e1.y;
            }
            *(float2*)(C + i0) = r01;
            *(float2*)(C + i1) = r23;
        }
    }
}

// ---------------- LayerNorm(x)*(1+scale)+shift -> bf16 hi/lo ---------------
__global__ void ln_film_kernel(const float* __restrict__ x,
                               const float* __restrict__ se,
                               __nv_bfloat16* __restrict__ hh,
                               __nv_bfloat16* __restrict__ hl)
{
    const int m = blockIdx.x;
    const float* xr = x + (size_t)m * CC;
    const float* sc = se + (size_t)m * (2 * CC);

    float v[4];
    float s = 0.f, s2 = 0.f;
    #pragma unroll
    for (int e = 0; e < 4; e++) {
        v[e] = xr[threadIdx.x + e * 256];
        s += v[e];
        s2 += v[e] * v[e];
    }
    __shared__ float shs[8], shs2[8], bcast[2];
    const int lane = threadIdx.x & 31, w = threadIdx.x >> 5;
    #pragma unroll
    for (int o = 16; o; o >>= 1) {
        s  += __shfl_xor_sync(0xffffffffu, s,  o);
        s2 += __shfl_xor_sync(0xffffffffu, s2, o);
    }
    if (lane == 0) { shs[w] = s; shs2[w] = s2; }
    __syncthreads();
    if (w == 0) {
        float a  = (lane < 8) ? shs[lane]  : 0.f;
        float a2 = (lane < 8) ? shs2[lane] : 0.f;
        #pragma unroll
        for (int o = 4; o; o >>= 1) {
            a  += __shfl_xor_sync(0xffffffffu, a,  o);
            a2 += __shfl_xor_sync(0xffffffffu, a2, o);
        }
        if (lane == 0) { bcast[0] = a; bcast[1] = a2; }
    }
    __syncthreads();
    const float mu  = bcast[0] * (1.f / CC);
    const float var = bcast[1] * (1.f / CC) - mu * mu;
    const float rs  = rsqrtf(var + EPSV);

    #pragma unroll
    for (int e = 0; e < 4; e++) {
        const int c = threadIdx.x + e * 256;
        const float hv = (v[e] - mu) * rs * (1.f + sc[c]) + sc[c + CC];
        __nv_bfloat16 hb, lb;
        split1(hv, hb, lb);
        hh[(size_t)m * CC + c] = hb;
        hl[(size_t)m * CC + c] = lb;
    }
}

// ---------------- qkv: per-head LN of q/k + split all to bf16 hi/lo --------
__global__ void qkv_ln_split(const float* __restrict__ qkv,
                             __nv_bfloat16* __restrict__ qh,
                             __nv_bfloat16* __restrict__ ql)
{
    const int seg  = blockIdx.x * 8 + (threadIdx.x >> 5);  // 8192*48 segments
    const int lane = threadIdx.x & 31;
    const int m = seg / 48;
    const int r = seg - m * 48;                            // 0..47
    const size_t off = (size_t)m * 3072 + r * 64;

    float a = qkv[off + lane];
    float b = qkv[off + lane + 32];
    if (r < 32) {  // q,k heads: normalize over 64
        float s = a + b, s2 = a * a + b * b;
        #pragma unroll
        for (int o = 16; o; o >>= 1) {
            s  += __shfl_xor_sync(0xffffffffu, s,  o);
            s2 += __shfl_xor_sync(0xffffffffu, s2, o);
        }
        const float mu  = s * (1.f / 64.f);
        const float var = s2 * (1.f / 64.f) - mu * mu;
        const float rs  = rsqrtf(var + EPSV);
        a = (a - mu) * rs;
        b = (b - mu) * rs;
    }
    __nv_bfloat16 ah, al, bh, bl;
    split1(a, ah, al);
    split1(b, bh, bl);
    qh[off + lane]      = ah; ql[off + lane]      = al;
    qh[off + lane + 32] = bh; ql[off + lane + 32] = bl;
}

// ---------------- flash attention (tensor-core, bf16x3, bf16 inputs) -------
#define FLD 72  // padded stride (bf16): 144B = 36 banks; conflict-free frags

#define QH_OFF 0
#define QL_OFF (128 * FLD)
#define KH_OFF (2 * 128 * FLD)
#define KL_OFF (KH_OFF + 64 * FLD)
#define VH_OFF (KL_OFF + 64 * FLD)
#define VL_OFF (VH_OFF + 64 * FLD)
#define FL_SMEM_BYTES ((VL_OFF + 64 * FLD) * 2)

__global__ void __launch_bounds__(256, 2)
flash_mma_kernel(const __nv_bfloat16* __restrict__ qkvh,
                 const __nv_bfloat16* __restrict__ qkvl,
                 float* __restrict__ o,
                 __nv_bfloat16* __restrict__ oh,
                 __nv_bfloat16* __restrict__ ol)
{
    extern __shared__ __nv_bfloat16 sm[];
    __nv_bfloat16* Qh = sm + QH_OFF;
    __nv_bfloat16* Ql = sm + QL_OFF;
    __nv_bfloat16* Kh = sm + KH_OFF;
    __nv_bfloat16* Kl = sm + KL_OFF;
    __nv_bfloat16* Vh = sm + VH_OFF;   // transposed: [d][pos]
    __nv_bfloat16* Vl = sm + VL_OFF;

    const int tid  = threadIdx.x;
    const int lane = tid & 31;
    const int wid  = tid >> 5;
    const int g    = lane >> 2;
    const int t    = lane & 3;

    const int b  = blockIdx.y >> 4;
    const int h  = blockIdx.y & 15;
    const int n0 = blockIdx.x * 128;

    const size_t hb_off = (size_t)b * NN * 3072 + h * 64;
    const __nv_bfloat16* qhg = qkvh + hb_off;
    const __nv_bfloat16* qlg = qkvl + hb_off;
    const __nv_bfloat16* khg = qhg + 1024;
    const __nv_bfloat16* klg = qlg + 1024;
    const __nv_bfloat16* vhg = qhg + 2048;
    const __nv_bfloat16* vlg = qlg + 2048;

    // ---- load Q tile (128x64) ----
    {
        const int lr = tid >> 1;
        const int c0 = (tid & 1) * 32;
        #pragma unroll
        for (int i = 0; i < 4; i++) {
            const int c = c0 + i * 8;
            const size_t goff = (size_t)(n0 + lr) * 3072 + c;
            *(uint4*)&Qh[lr * FLD + c] = *(const uint4*)(qhg + goff);
            *(uint4*)&Ql[lr * FLD + c] = *(const uint4*)(qlg + goff);
        }
    }

    float oacc[8][4];
    #pragma unroll
    for (int nb = 0; nb < 8; nb++)
        #pragma unroll
        for (int e = 0; e < 4; e++) oacc[nb][e] = 0.f;
    float m0r = -1e30f, m1r = -1e30f, l0r = 0.f, l1r = 0.f;

    const float scl = 0.125f * 1.44269504088896f;  // 1/sqrt(D) * log2(e)

    for (int kt = 0; kt < NN; kt += 64) {
        __syncthreads();
        // ---- load K (row-major) + V (transposed) tiles ----
        {
            const int lr = tid >> 2;
            const int c0 = (tid & 3) * 16;
            #pragma unroll
            for (int i = 0; i < 2; i++) {
                const int c = c0 + i * 8;
                const size_t goff = (size_t)(kt + lr) * 3072 + c;
                *(uint4*)&Kh[lr * FLD + c] = *(const uint4*)(khg + goff);
                *(uint4*)&Kl[lr * FLD + c] = *(const uint4*)(klg + goff);
            }
            #pragma unroll
            for (int i = 0; i < 2; i++) {
                const int c = c0 + i * 8;
                const size_t goff = (size_t)(kt + lr) * 3072 + c;
                uint4 ph = *(const uint4*)(vhg + goff);
                uint4 pl = *(const uint4*)(vlg + goff);
                const __nv_bfloat16* pb = (const __nv_bfloat16*)&ph;
                const __nv_bfloat16* qb = (const __nv_bfloat16*)&pl;
                #pragma unroll
                for (int j = 0; j < 8; j++) {
                    Vh[(c + j) * FLD + lr] = pb[j];
                    Vl[(c + j) * FLD + lr] = qb[j];
                }
            }
        }
        __syncthreads();

        // ---- S = Q K^T (bf16x3) ----
        float sacc[8][4];
        #pragma unroll
        for (int nb = 0; nb < 8; nb++)
            #pragma unroll
            for (int e = 0; e < 4; e++) sacc[nb][e] = 0.f;

        #pragma unroll
        for (int kk = 0; kk < 4; kk++) {
            uint32_t ah[4], al[4];
            const int ab = (wid * 16 + g) * FLD + kk * 16 + t * 2;
            ah[0] = *(const uint32_t*)&Qh[ab];
            ah[1] = *(const uint32_t*)&Qh[ab + 8 * FLD];
            ah[2] = *(const uint32_t*)&Qh[ab + 8];
            ah[3] = *(const uint32_t*)&Qh[ab + 8 * FLD + 8];
            al[0] = *(const uint32_t*)&Ql[ab];
            al[1] = *(const uint32_t*)&Ql[ab + 8 * FLD];
            al[2] = *(const uint32_t*)&Ql[ab + 8];
            al[3] = *(const uint32_t*)&Ql[ab + 8 * FLD + 8];
            #pragma unroll
            for (int nb = 0; nb < 8; nb++) {
                uint32_t bh[2], bl[2];
                const int bbse = (nb * 8 + g) * FLD + kk * 16 + t * 2;
                bh[0] = *(const uint32_t*)&Kh[bbse];
                bh[1] = *(const uint32_t*)&Kh[bbse + 8];
                bl[0] = *(const uint32_t*)&Kl[bbse];
                bl[1] = *(const uint32_t*)&Kl[bbse + 8];
                mma16816(sacc[nb], ah, bh);
                mma16816(sacc[nb], ah, bl);
                mma16816(sacc[nb], al, bh);
            }
        }

        // ---- online softmax ----
        float mx0 = -1e30f, mx1 = -1e30f;
        #pragma unroll
        for (int nb = 0; nb < 8; nb++) {
            sacc[nb][0] *= scl; sacc[nb][1] *= scl;
            sacc[nb][2] *= scl; sacc[nb][3] *= scl;
            mx0 = fmaxf(mx0, fmaxf(sacc[nb][0], sacc[nb][1]));
            mx1 = fmaxf(mx1, fmaxf(sacc[nb][2], sacc[nb][3]));
        }
        mx0 = fmaxf(mx0, __shfl_xor_sync(0xffffffffu, mx0, 1));
        mx0 = fmaxf(mx0, __shfl_xor_sync(0xffffffffu, mx0, 2));
        mx1 = fmaxf(mx1, __shfl_xor_sync(0xffffffffu, mx1, 1));
        mx1 = fmaxf(mx1, __shfl_xor_sync(0xffffffffu, mx1, 2));
        const float mn0 = fmaxf(m0r, mx0);
        const float mn1 = fmaxf(m1r, mx1);
        const float co0 = ex2f(m0r - mn0);
        const float co1 = ex2f(m1r - mn1);
        m0r = mn0; m1r = mn1;
        l0r *= co0; l1r *= co1;
        #pragma unroll
        for (int nb = 0; nb < 8; nb++) {
            oacc[nb][0] *= co0; oacc[nb][1] *= co0;
            oacc[nb][2] *= co1; oacc[nb][3] *= co1;
        }
        float rs0 = 0.f, rs1 = 0.f;
        #pragma unroll
        for (int nb = 0; nb < 8; nb++) {
            sacc[nb][0] = ex2f(sacc[nb][0] - mn0);
            sacc[nb][1] = ex2f(sacc[nb][1] - mn0);
            sacc[nb][2] = ex2f(sacc[nb][2] - mn1);
            sacc[nb][3] = ex2f(sacc[nb][3] - mn1);
            rs0 += sacc[nb][0] + sacc[nb][1];
            rs1 += sacc[nb][2] + sacc[nb][3];
        }
        rs0 += __shfl_xor_sync(0xffffffffu, rs0, 1);
        rs0 += __shfl_xor_sync(0xffffffffu, rs0, 2);
        rs1 += __shfl_xor_sync(0xffffffffu, rs1, 1);
        rs1 += __shfl_xor_sync(0xffffffffu, rs1, 2);
        l0r += rs0; l1r += rs1;

        // ---- O += P V ----
        #pragma unroll
        for (int kbk = 0; kbk < 4; kbk++) {
            uint32_t pah[4], pal[4];
            #pragma unroll
            for (int half = 0; half < 2; half++) {
                const float p0 = sacc[2 * kbk + half][0];
                const float p1 = sacc[2 * kbk + half][1];
                const float p2 = sacc[2 * kbk + half][2];
                const float p3 = sacc[2 * kbk + half][3];
                __nv_bfloat162 hA, hB, lA, lB;
                split1(p0, hA.x, lA.x); split1(p1, hA.y, lA.y);
                split1(p2, hB.x, lB.x); split1(p3, hB.y, lB.y);
                pah[0 + 2 * half] = *(const uint32_t*)&hA;
                pah[1 + 2 * half] = *(const uint32_t*)&hB;
                pal[0 + 2 * half] = *(const uint32_t*)&lA;
                pal[1 + 2 * half] = *(const uint32_t*)&lB;
            }
            #pragma unroll
            for (int nb = 0; nb < 8; nb++) {
                uint32_t vh[2], vl[2];
                const int vbse = (nb * 8 + g) * FLD + kbk * 16 + t * 2;
                vh[0] = *(const uint32_t*)&Vh[vbse];
                vh[1] = *(const uint32_t*)&Vh[vbse + 8];
                vl[0] = *(const uint32_t*)&Vl[vbse];
                vl[1] = *(const uint32_t*)&Vl[vbse + 8];
                mma16816(oacc[nb], pah, vh);
                mma16816(oacc[nb], pah, vl);
                mma16816(oacc[nb], pal, vh);
            }
        }
    }

    // ---- epilogue: write o fp32 + hi/lo ----
    const float inv0 = 1.f / l0r;
    const float inv1 = 1.f / l1r;
    const int row0 = n0 + wid * 16 + g;
    const int row1 = row0 + 8;
    const size_t obase = (size_t)b * NN * CC + h * 64;
    #pragma unroll
    for (int nb = 0; nb < 8; nb++) {
        const int col = nb * 8 + t * 2;
        float2 r0, r1;
        r0.x = oacc[nb][0] * inv0; r0.y = oacc[nb][1] * inv0;
        r1.x = oacc[nb][2] * inv1; r1.y = oacc[nb][3] * inv1;
        const size_t i0 = obase + (size_t)row0 * CC + col;
        const size_t i1 = obase + (size_t)row1 * CC + col;
        *(float2*)(o + i0) = r0;
        *(float2*)(o + i1) = r1;
        __nv_bfloat162 h0, l0, h1, l1;
        split1(r0.x, h0.x, l0.x); split1(r0.y, h0.y, l0.y);
        split1(r1.x, h1.x, l1.x); split1(r1.y, h1.y, l1.y);
        *(__nv_bfloat162*)(oh + i0) = h0;
        *(__nv_bfloat162*)(ol + i0) = l0;
        *(__nv_bfloat162*)(oh + i1) = h1;
        *(__nv_bfloat162*)(ol + i1) = l1;
    }
}

// ---------------- launcher -------------------------------------------------
extern "C" void kernel_launch(void* const* d_in, const int* in_sizes, int n_in,
                              void* d_out, int out_size)
{
    const float* x      = (const float*)d_in[0];
    const float* emb    = (const float*)d_in[1];
    const float* W_emb  = (const float*)d_in[2];
    const float* b_emb  = (const float*)d_in[3];
    const float* W_proj = (const float*)d_in[4];
    const float* W_out  = (const float*)d_in[5];
    float* out = (float*)d_out;

    float *se, *qkv, *o;
    __nv_bfloat16 *embh, *embl, *hh, *hl, *qkvh, *qkvl, *oh, *ol;
    __nv_bfloat16 *Wembh, *Wembl, *Wprjh, *Wprjl, *Wouth, *Woutl;
    cudaGetSymbolAddress((void**)&se,   g_se);
    cudaGetSymbolAddress((void**)&qkv,  g_qkv);
    cudaGetSymbolAddress((void**)&o,    g_o);
    cudaGetSymbolAddress((void**)&embh, g_embh);
    cudaGetSymbolAddress((void**)&embl, g_embl);
    cudaGetSymbolAddress((void**)&hh,   g_hh);
    cudaGetSymbolAddress((void**)&hl,   g_hl);
    cudaGetSymbolAddress((void**)&qkvh, g_qkvh);
    cudaGetSymbolAddress((void**)&qkvl, g_qkvl);
    cudaGetSymbolAddress((void**)&oh,   g_oh);
    cudaGetSymbolAddress((void**)&ol,   g_ol);
    cudaGetSymbolAddress((void**)&Wembh, g_Wembh);
    cudaGetSymbolAddress((void**)&Wembl, g_Wembl);
    cudaGetSymbolAddress((void**)&Wprjh, g_Wprjh);
    cudaGetSymbolAddress((void**)&Wprjl, g_Wprjl);
    cudaGetSymbolAddress((void**)&Wouth, g_Wouth);
    cudaGetSymbolAddress((void**)&Woutl, g_Woutl);

    static int attr_set = 0;
    if (!attr_set) {
        cudaFuncSetAttribute(flash_mma_kernel,
                             cudaFuncAttributeMaxDynamicSharedMemorySize, FL_SMEM_BYTES);
        cudaFuncSetAttribute(bgemm_bb<0>,
                             cudaFuncAttributeMaxDynamicSharedMemorySize, GEMM_SMEM_BYTES);
        cudaFuncSetAttribute(bgemm_bb<1>,
                             cudaFuncAttributeMaxDynamicSharedMemorySize, GEMM_SMEM_BYTES);
        cudaFuncSetAttribute(bgemm_bb<2>,
                             cudaFuncAttributeMaxDynamicSharedMemorySize, GEMM_SMEM_BYTES);
        attr_set = 1;
    }

    // 0) split inputs/weights to bf16 hi/lo
    split_kernel<<<(MM * 1024 / 4) / 256, 256>>>((const float4*)emb, (uint2*)embh, (uint2*)embl, MM * 1024 / 4);
    split_kernel<<<(2048 * 1024 / 4) / 256, 256>>>((const float4*)W_emb, (uint2*)Wembh, (uint2*)Wembl, 2048 * 1024 / 4);
    split_kernel<<<(3072 * 1024 / 4) / 256, 256>>>((const float4*)W_proj, (uint2*)Wprjh, (uint2*)Wprjl, 3072 * 1024 / 4);
    split_kernel<<<(1024 * 1024 / 4) / 256, 256>>>((const float4*)W_out, (uint2*)Wouth, (uint2*)Woutl, 1024 * 1024 / 4);

    // 1) se = emb @ W_emb^T + b_emb
    bgemm_bb<0><<<dim3(2048 / 64, MM / 128), 256, GEMM_SMEM_BYTES>>>(
        embh, embl, Wembh, Wembl, se, 2048, EMB, b_emb);
    // 2) h = LN(x)*(1+scale)+shift -> bf16 hi/lo
    ln_film_kernel<<<MM, 256>>>(x, se, hh, hl);
    // 3) qkv = h @ W_proj^T (fp32)
    bgemm_bb<1><<<dim3(3072 / 64, MM / 128), 256, GEMM_SMEM_BYTES>>>(
        hh, hl, Wprjh, Wprjl, qkv, 3072, CC, nullptr);
    // 4) q/k LN + full qkv split -> bf16 hi/lo
    qkv_ln_split<<<(MM * 48) / 8, 256>>>(qkv, qkvh, qkvl);
    // 5) flash attention -> o fp32 + bf16 hi/lo
    flash_mma_kernel<<<dim3(NN / 128, BB * HH), 256, FL_SMEM_BYTES>>>(qkvh, qkvl, o, oh, ol);
    // 6) out = o + o @ W_out^T
    bgemm_bb<2><<<dim3(1024 / 64, MM / 128), 256, GEMM_SMEM_BYTES>>>(
        oh, ol, Wouth, Woutl, out, 1024, CC, o);
}

// round 12
// speedup vs baseline: 7.5321x; 1.9390x over previous
#include <cuda_runtime.h>
#include <cuda_fp16.h>
#include <cstdint>

// Problem constants
#define BB 4
#define NN 2048
#define CC 1024
#define HH 16
#define DD 64
#define MM (BB*NN)          // 8192 token rows
#define EMB 1024
#define EPSV 1e-5f

// ---------------- scratch (device globals; no allocation allowed) ----------
__device__ float g_se [(size_t)MM * 2048];              // 64 MB
__device__ float g_qkv[(size_t)MM * 3072];              // 96 MB
__device__ float g_o  [(size_t)MM * 1024];              // 32 MB
__device__ __half g_embf[(size_t)MM * 1024];            // 16 MB
__device__ __half g_hf  [(size_t)MM * 1024];            // 16 MB
__device__ __half g_qkvf[(size_t)MM * 3072];            // 48 MB
__device__ __half g_of  [(size_t)MM * 1024];            // 16 MB
__device__ __half g_Wembf[2048 * 1024];
__device__ __half g_Wprjf[3072 * 1024];
__device__ __half g_Woutf[1024 * 1024];

// ---------------- helpers --------------------------------------------------
__device__ __forceinline__ void mma16816(float* c, const uint32_t* a, const uint32_t* b)
{
    asm volatile(
        "mma.sync.aligned.m16n8k16.row.col.f32.f16.f16.f32 "
        "{%0,%1,%2,%3}, {%4,%5,%6,%7}, {%8,%9}, {%0,%1,%2,%3};\n"
        : "+f"(c[0]), "+f"(c[1]), "+f"(c[2]), "+f"(c[3])
        : "r"(a[0]), "r"(a[1]), "r"(a[2]), "r"(a[3]), "r"(b[0]), "r"(b[1]));
}

__device__ __forceinline__ float ex2f(float x)
{
    float r;
    asm("ex2.approx.f32 %0, %1;" : "=f"(r) : "f"(x));
    return r;
}

__device__ __forceinline__ void cp_async16(void* s, const void* g)
{
    uint32_t sa = (uint32_t)__cvta_generic_to_shared(s);
    asm volatile("cp.async.cg.shared.global [%0], [%1], 16;\n" :: "r"(sa), "l"(g));
}

// ---------------- convert pass: fp32 -> fp16 -------------------------------
__global__ void cvt_kernel(const float4* __restrict__ src, uint2* __restrict__ dst, int n4)
{
    const int i = blockIdx.x * 256 + threadIdx.x;
    if (i >= n4) return;
    float4 v = src[i];
    __half2 a = __floats2half2_rn(v.x, v.y);
    __half2 b = __floats2half2_rn(v.z, v.w);
    uint2 o;
    o.x = *(const uint32_t*)&a;
    o.y = *(const uint32_t*)&b;
    dst[i] = o;
}

// ---------------- fp16 GEMM, cp.async 2-stage: C = A(MxK)*B(NxK)^T ---------
// EPI 0: +bias[n]; 1: none; 2: +extra[m*N+n]
#define LDA 40                // padded row stride (halves): 80B = 20 banks
#define STG_ELEMS 7680        // per-stage halves: A 128*40 | B 64*40
#define GEMM_SMEM_BYTES (2 * STG_ELEMS * 2)

template<int EPI>
__global__ void __launch_bounds__(256, 2)
fgemm(const __half* __restrict__ A_g, const __half* __restrict__ B_g,
      float* __restrict__ C, int N, int K, const float* __restrict__ extra)
{
    extern __shared__ __half smem[];

    const int tid  = threadIdx.x;
    const int lane = tid & 31;
    const int wid  = tid >> 5;
    const int g    = lane >> 2;
    const int t    = lane & 3;
    const int wm   = wid >> 1;
    const int wn   = wid & 1;

    const int m0 = blockIdx.y * 128;
    const int n0 = blockIdx.x * 64;

    float acc[2][4][4];
    #pragma unroll
    for (int mi = 0; mi < 2; mi++)
        #pragma unroll
        for (int ni = 0; ni < 4; ni++)
            #pragma unroll
            for (int e = 0; e < 4; e++) acc[mi][ni][e] = 0.f;

    const int arow = tid >> 2;            // 0..63
    const int ach  = (tid & 3) * 8;       // half chunk 0,8,16,24

    auto issue_stage = [&](int st, int k0) {
        __half* sa = smem + st * STG_ELEMS;
        __half* sb = sa + 5120;
        #pragma unroll
        for (int rep = 0; rep < 2; rep++) {
            const int row = arow + rep * 64;
            cp_async16(&sa[row * LDA + ach], A_g + (size_t)(m0 + row) * K + k0 + ach);
        }
        cp_async16(&sb[arow * LDA + ach], B_g + (size_t)(n0 + arow) * K + k0 + ach);
        asm volatile("cp.async.commit_group;\n");
    };

    const int KT = K >> 5;
    issue_stage(0, 0);

    for (int kt = 0; kt < KT; kt++) {
        if (kt + 1 < KT) {
            issue_stage((kt + 1) & 1, (kt + 1) << 5);
            asm volatile("cp.async.wait_group 1;\n");
        } else {
            asm volatile("cp.async.wait_group 0;\n");
        }
        __syncthreads();

        const __half* As = smem + (kt & 1) * STG_ELEMS;
        const __half* Bs = As + 5120;

        #pragma unroll
        for (int kk = 0; kk < 32; kk += 16) {
            uint32_t af[2][4];
            #pragma unroll
            for (int mi = 0; mi < 2; mi++) {
                const int r0 = (wm * 32 + mi * 16 + g) * LDA + kk + t * 2;
                const int r1 = r0 + 8 * LDA;
                af[mi][0] = *(const uint32_t*)&As[r0];
                af[mi][1] = *(const uint32_t*)&As[r1];
                af[mi][2] = *(const uint32_t*)&As[r0 + 8];
                af[mi][3] = *(const uint32_t*)&As[r1 + 8];
            }
            uint32_t bf[4][2];
            #pragma unroll
            for (int ni = 0; ni < 4; ni++) {
                const int r = (wn * 32 + ni * 8 + g) * LDA + kk + t * 2;
                bf[ni][0] = *(const uint32_t*)&Bs[r];
                bf[ni][1] = *(const uint32_t*)&Bs[r + 8];
            }
            #pragma unroll
            for (int mi = 0; mi < 2; mi++)
                #pragma unroll
                for (int ni = 0; ni < 4; ni++)
                    mma16816(acc[mi][ni], af[mi], bf[ni]);
        }
        __syncthreads();
    }

    #pragma unroll
    for (int mi = 0; mi < 2; mi++) {
        const int row0 = m0 + wm * 32 + mi * 16 + g;
        #pragma unroll
        for (int ni = 0; ni < 4; ni++) {
            const int col = n0 + wn * 32 + ni * 8 + t * 2;
            float2 r01, r23;
            r01.x = acc[mi][ni][0]; r01.y = acc[mi][ni][1];
            r23.x = acc[mi][ni][2]; r23.y = acc[mi][ni][3];
            const size_t i0 = (size_t)row0 * N + col;
            const size_t i1 = (size_t)(row0 + 8) * N + col;
            if (EPI == 0) {
                float2 bv = *(const float2*)(extra + col);
                r01.x += bv.x; r01.y += bv.y;
                r23.x += bv.x; r23.y += bv.y;
            } else if (EPI == 2) {
                float2 e0 = *(const float2*)(extra + i0);
                float2 e1 = *(const float2*)(extra + i1);
                r01.x += e0.x; r01.y += e0.y;
                r23.x += e1.x; r23.y += e1.y;
            }
            *(float2*)(C + i0) = r01;
            *(float2*)(C + i1) = r23;
        }
    }
}

// ---------------- LayerNorm(x)*(1+scale)+shift -> fp16 ---------------------
__global__ void ln_film_kernel(const float* __restrict__ x,
                               const float* __restrict__ se,
                               __half* __restrict__ hf)
{
    const int m = blockIdx.x;
    const float* xr = x + (size_t)m * CC;
    const float* sc = se + (size_t)m * (2 * CC);

    float v[4];
    float s = 0.f, s2 = 0.f;
    #pragma unroll
    for (int e = 0; e < 4; e++) {
        v[e] = xr[threadIdx.x + e * 256];
        s += v[e];
        s2 += v[e] * v[e];
    }
    __shared__ float shs[8], shs2[8], bcast[2];
    const int lane = threadIdx.x & 31, w = threadIdx.x >> 5;
    #pragma unroll
    for (int o = 16; o; o >>= 1) {
        s  += __shfl_xor_sync(0xffffffffu, s,  o);
        s2 += __shfl_xor_sync(0xffffffffu, s2, o);
    }
    if (lane == 0) { shs[w] = s; shs2[w] = s2; }
    __syncthreads();
    if (w == 0) {
        float a  = (lane < 8) ? shs[lane]  : 0.f;
        float a2 = (lane < 8) ? shs2[lane] : 0.f;
        #pragma unroll
        for (int o = 4; o; o >>= 1) {
            a  += __shfl_xor_sync(0xffffffffu, a,  o);
            a2 += __shfl_xor_sync(0xffffffffu, a2, o);
        }
        if (lane == 0) { bcast[0] = a; bcast[1] = a2; }
    }
    __syncthreads();
    const float mu  = bcast[0] * (1.f / CC);
    const float var = bcast[1] * (1.f / CC) - mu * mu;
    const float rs  = rsqrtf(var + EPSV);

    #pragma unroll
    for (int e = 0; e < 4; e++) {
        const int c = threadIdx.x + e * 256;
        const float hv = (v[e] - mu) * rs * (1.f + sc[c]) + sc[c + CC];
        hf[(size_t)m * CC + c] = __float2half_rn(hv);
    }
}

// ---------------- qkv: per-head LN of q/k + convert all to fp16 ------------
__global__ void qkv_ln_cvt(const float* __restrict__ qkv,
                           __half* __restrict__ qf)
{
    const int seg  = blockIdx.x * 8 + (threadIdx.x >> 5);  // 8192*48 segments
    const int lane = threadIdx.x & 31;
    const int m = seg / 48;
    const int r = seg - m * 48;                            // 0..47
    const size_t off = (size_t)m * 3072 + r * 64;

    float a = qkv[off + lane];
    float b = qkv[off + lane + 32];
    if (r < 32) {  // q,k heads: normalize over 64
        float s = a + b, s2 = a * a + b * b;
        #pragma unroll
        for (int o = 16; o; o >>= 1) {
            s  += __shfl_xor_sync(0xffffffffu, s,  o);
            s2 += __shfl_xor_sync(0xffffffffu, s2, o);
        }
        const float mu  = s * (1.f / 64.f);
        const float var = s2 * (1.f / 64.f) - mu * mu;
        const float rs  = rsqrtf(var + EPSV);
        a = (a - mu) * rs;
        b = (b - mu) * rs;
    }
    qf[off + lane]      = __float2half_rn(a);
    qf[off + lane + 32] = __float2half_rn(b);
}

// ---------------- flash attention (fp16 mma) -------------------------------
#define FLD 72  // padded stride (halves): 144B = 36 banks; conflict-free frags

#define QF_OFF 0
#define KF_OFF (128 * FLD)
#define VF_OFF (KF_OFF + 64 * FLD)
#define FL_SMEM_BYTES ((VF_OFF + 64 * FLD) * 2)

__global__ void __launch_bounds__(256, 2)
flash_mma_kernel(const __half* __restrict__ qkvf,
                 float* __restrict__ o,
                 __half* __restrict__ of)
{
    extern __shared__ __half sm[];
    __half* Qf = sm + QF_OFF;
    __half* Kf = sm + KF_OFF;
    __half* Vf = sm + VF_OFF;   // transposed: [d][pos]

    const int tid  = threadIdx.x;
    const int lane = tid & 31;
    const int wid  = tid >> 5;
    const int g    = lane >> 2;
    const int t    = lane & 3;

    const int b  = blockIdx.y >> 4;
    const int h  = blockIdx.y & 15;
    const int n0 = blockIdx.x * 128;

    const size_t hb_off = (size_t)b * NN * 3072 + h * 64;
    const __half* qg = qkvf + hb_off;
    const __half* kg = qg + 1024;
    const __half* vg = qg + 2048;

    // ---- load Q tile (128x64) ----
    {
        const int lr = tid >> 1;
        const int c0 = (tid & 1) * 32;
        #pragma unroll
        for (int i = 0; i < 4; i++) {
            const int c = c0 + i * 8;
            *(uint4*)&Qf[lr * FLD + c] = *(const uint4*)(qg + (size_t)(n0 + lr) * 3072 + c);
        }
    }

    float oacc[8][4];
    #pragma unroll
    for (int nb = 0; nb < 8; nb++)
        #pragma unroll
        for (int e = 0; e < 4; e++) oacc[nb][e] = 0.f;
    float m0r = -1e30f, m1r = -1e30f, l0r = 0.f, l1r = 0.f;

    const float scl = 0.125f * 1.44269504088896f;  // 1/sqrt(D) * log2(e)

    for (int kt = 0; kt < NN; kt += 64) {
        __syncthreads();
        // ---- load K (row-major) + V (transposed) tiles ----
        {
            const int lr = tid >> 2;
            const int c0 = (tid & 3) * 16;
            #pragma unroll
            for (int i = 0; i < 2; i++) {
                const int c = c0 + i * 8;
                *(uint4*)&Kf[lr * FLD + c] = *(const uint4*)(kg + (size_t)(kt + lr) * 3072 + c);
            }
            #pragma unroll
            for (int i = 0; i < 2; i++) {
                const int c = c0 + i * 8;
                uint4 pv = *(const uint4*)(vg + (size_t)(kt + lr) * 3072 + c);
                const __half* pb = (const __half*)&pv;
                #pragma unroll
                for (int j = 0; j < 8; j++)
                    Vf[(c + j) * FLD + lr] = pb[j];
            }
        }
        __syncthreads();

        // ---- S = Q K^T ----
        float sacc[8][4];
        #pragma unroll
        for (int nb = 0; nb < 8; nb++)
            #pragma unroll
            for (int e = 0; e < 4; e++) sacc[nb][e] = 0.f;

        #pragma unroll
        for (int kk = 0; kk < 4; kk++) {
            uint32_t af[4];
            const int ab = (wid * 16 + g) * FLD + kk * 16 + t * 2;
            af[0] = *(const uint32_t*)&Qf[ab];
            af[1] = *(const uint32_t*)&Qf[ab + 8 * FLD];
            af[2] = *(const uint32_t*)&Qf[ab + 8];
            af[3] = *(const uint32_t*)&Qf[ab + 8 * FLD + 8];
            #pragma unroll
            for (int nb = 0; nb < 8; nb++) {
                uint32_t bf[2];
                const int bbse = (nb * 8 + g) * FLD + kk * 16 + t * 2;
                bf[0] = *(const uint32_t*)&Kf[bbse];
                bf[1] = *(const uint32_t*)&Kf[bbse + 8];
                mma16816(sacc[nb], af, bf);
            }
        }

        // ---- online softmax ----
        float mx0 = -1e30f, mx1 = -1e30f;
        #pragma unroll
        for (int nb = 0; nb < 8; nb++) {
            sacc[nb][0] *= scl; sacc[nb][1] *= scl;
            sacc[nb][2] *= scl; sacc[nb][3] *= scl;
            mx0 = fmaxf(mx0, fmaxf(sacc[nb][0], sacc[nb][1]));
            mx1 = fmaxf(mx1, fmaxf(sacc[nb][2], sacc[nb][3]));
        }
        mx0 = fmaxf(mx0, __shfl_xor_sync(0xffffffffu, mx0, 1));
        mx0 = fmaxf(mx0, __shfl_xor_sync(0xffffffffu, mx0, 2));
        mx1 = fmaxf(mx1, __shfl_xor_sync(0xffffffffu, mx1, 1));
        mx1 = fmaxf(mx1, __shfl_xor_sync(0xffffffffu, mx1, 2));
        const float mn0 = fmaxf(m0r, mx0);
        const float mn1 = fmaxf(m1r, mx1);
        const float co0 = ex2f(m0r - mn0);
        const float co1 = ex2f(m1r - mn1);
        m0r = mn0; m1r = mn1;
        l0r *= co0; l1r *= co1;
        #pragma unroll
        for (int nb = 0; nb < 8; nb++) {
            oacc[nb][0] *= co0; oacc[nb][1] *= co0;
            oacc[nb][2] *= co1; oacc[nb][3] *= co1;
        }
        float rs0 = 0.f, rs1 = 0.f;
        #pragma unroll
        for (int nb = 0; nb < 8; nb++) {
            sacc[nb][0] = ex2f(sacc[nb][0] - mn0);
            sacc[nb][1] = ex2f(sacc[nb][1] - mn0);
            sacc[nb][2] = ex2f(sacc[nb][2] - mn1);
            sacc[nb][3] = ex2f(sacc[nb][3] - mn1);
            rs0 += sacc[nb][0] + sacc[nb][1];
            rs1 += sacc[nb][2] + sacc[nb][3];
        }
        rs0 += __shfl_xor_sync(0xffffffffu, rs0, 1);
        rs0 += __shfl_xor_sync(0xffffffffu, rs0, 2);
        rs1 += __shfl_xor_sync(0xffffffffu, rs1, 1);
        rs1 += __shfl_xor_sync(0xffffffffu, rs1, 2);
        l0r += rs0; l1r += rs1;

        // ---- O += P V ----
        #pragma unroll
        for (int kbk = 0; kbk < 4; kbk++) {
            uint32_t pa[4];
            #pragma unroll
            for (int half = 0; half < 2; half++) {
                __half2 hA = __floats2half2_rn(sacc[2 * kbk + half][0],
                                               sacc[2 * kbk + half][1]);
                __half2 hB = __floats2half2_rn(sacc[2 * kbk + half][2],
                                               sacc[2 * kbk + half][3]);
                pa[0 + 2 * half] = *(const uint32_t*)&hA;
                pa[1 + 2 * half] = *(const uint32_t*)&hB;
            }
            #pragma unroll
            for (int nb = 0; nb < 8; nb++) {
                uint32_t vf[2];
                const int vbse = (nb * 8 + g) * FLD + kbk * 16 + t * 2;
                vf[0] = *(const uint32_t*)&Vf[vbse];
                vf[1] = *(const uint32_t*)&Vf[vbse + 8];
                mma16816(oacc[nb], pa, vf);
            }
        }
    }

    // ---- epilogue: write o fp32 + fp16 ----
    const float inv0 = 1.f / l0r;
    const float inv1 = 1.f / l1r;
    const int row0 = n0 + wid * 16 + g;
    const int row1 = row0 + 8;
    const size_t obase = (size_t)b * NN * CC + h * 64;
    #pragma unroll
    for (int nb = 0; nb < 8; nb++) {
        const int col = nb * 8 + t * 2;
        float2 r0, r1;
        r0.x = oacc[nb][0] * inv0; r0.y = oacc[nb][1] * inv0;
        r1.x = oacc[nb][2] * inv1; r1.y = oacc[nb][3] * inv1;
        const size_t i0 = obase + (size_t)row0 * CC + col;
        const size_t i1 = obase + (size_t)row1 * CC + col;
        *(float2*)(o + i0) = r0;
        *(float2*)(o + i1) = r1;
        __half2 f0 = __floats2half2_rn(r0.x, r0.y);
        __half2 f1 = __floats2half2_rn(r1.x, r1.y);
        *(__half2*)(of + i0) = f0;
        *(__half2*)(of + i1) = f1;
    }
}

// ---------------- launcher -------------------------------------------------
extern "C" void kernel_launch(void* const* d_in, const int* in_sizes, int n_in,
                              void* d_out, int out_size)
{
    const float* x      = (const float*)d_in[0];
    const float* emb    = (const float*)d_in[1];
    const float* W_emb  = (const float*)d_in[2];
    const float* b_emb  = (const float*)d_in[3];
    const float* W_proj = (const float*)d_in[4];
    const float* W_out  = (const float*)d_in[5];
    float* out = (float*)d_out;

    float *se, *qkv, *o;
    __half *embf, *hf, *qkvf, *of, *Wembf, *Wprjf, *Woutf;
    cudaGetSymbolAddress((void**)&se,    g_se);
    cudaGetSymbolAddress((void**)&qkv,   g_qkv);
    cudaGetSymbolAddress((void**)&o,     g_o);
    cudaGetSymbolAddress((void**)&embf,  g_embf);
    cudaGetSymbolAddress((void**)&hf,    g_hf);
    cudaGetSymbolAddress((void**)&qkvf,  g_qkvf);
    cudaGetSymbolAddress((void**)&of,    g_of);
    cudaGetSymbolAddress((void**)&Wembf, g_Wembf);
    cudaGetSymbolAddress((void**)&Wprjf, g_Wprjf);
    cudaGetSymbolAddress((void**)&Woutf, g_Woutf);

    // idempotent, capture-safe, no call-count-dependent behavior
    cudaFuncSetAttribute(flash_mma_kernel,
                         cudaFuncAttributeMaxDynamicSharedMemorySize, FL_SMEM_BYTES);
    cudaFuncSetAttribute(fgemm<0>,
                         cudaFuncAttributeMaxDynamicSharedMemorySize, GEMM_SMEM_BYTES);
    cudaFuncSetAttribute(fgemm<1>,
                         cudaFuncAttributeMaxDynamicSharedMemorySize, GEMM_SMEM_BYTES);
    cudaFuncSetAttribute(fgemm<2>,
                         cudaFuncAttributeMaxDynamicSharedMemorySize, GEMM_SMEM_BYTES);

    // 0) convert inputs/weights to fp16
    cvt_kernel<<<(MM * 1024 / 4) / 256, 256>>>((const float4*)emb, (uint2*)embf, MM * 1024 / 4);
    cvt_kernel<<<(2048 * 1024 / 4) / 256, 256>>>((const float4*)W_emb, (uint2*)Wembf, 2048 * 1024 / 4);
    cvt_kernel<<<(3072 * 1024 / 4) / 256, 256>>>((const float4*)W_proj, (uint2*)Wprjf, 3072 * 1024 / 4);
    cvt_kernel<<<(1024 * 1024 / 4) / 256, 256>>>((const float4*)W_out, (uint2*)Woutf, 1024 * 1024 / 4);

    // 1) se = emb @ W_emb^T + b_emb
    fgemm<0><<<dim3(2048 / 64, MM / 128), 256, GEMM_SMEM_BYTES>>>(
        embf, Wembf, se, 2048, EMB, b_emb);
    // 2) h = LN(x)*(1+scale)+shift -> fp16
    ln_film_kernel<<<MM, 256>>>(x, se, hf);
    // 3) qkv = h @ W_proj^T (fp32 out)
    fgemm<1><<<dim3(3072 / 64, MM / 128), 256, GEMM_SMEM_BYTES>>>(
        hf, Wprjf, qkv, 3072, CC, nullptr);
    // 4) q/k LN + convert all qkv to fp16
    qkv_ln_cvt<<<(MM * 48) / 8, 256>>>(qkv, qkvf);
    // 5) flash attention -> o fp32 + fp16
    flash_mma_kernel<<<dim3(NN / 128, BB * HH), 256, FL_SMEM_BYTES>>>(qkvf, o, of);
    // 6) out = o + o @ W_out^T
    fgemm<2><<<dim3(1024 / 64, MM / 128), 256, GEMM_SMEM_BYTES>>>(
        of, Woutf, out, 1024, CC, o);
}

// round 15
// speedup vs baseline: 7.9328x; 1.0532x over previous
#include <cuda_runtime.h>
#include <cuda_fp16.h>
#include <cstdint>

// Problem constants
#define BB 4
#define NN 2048
#define CC 1024
#define HH 16
#define DD 64
#define MM (BB*NN)          // 8192 token rows
#define EMB 1024
#define EPSV 1e-5f

// ---------------- scratch (device globals; no allocation allowed) ----------
__device__ float g_se [(size_t)MM * 2048];              // 64 MB
__device__ __half g_embf[(size_t)MM * 1024];            // 16 MB
__device__ __half g_hf  [(size_t)MM * 1024];            // 16 MB
__device__ __half g_qkvf[(size_t)MM * 3072];            // 48 MB
__device__ __half g_of  [(size_t)MM * 1024];            // 16 MB
__device__ __half g_Wembf[2048 * 1024];
__device__ __half g_Wprjf[3072 * 1024];
__device__ __half g_Woutf[1024 * 1024];

// ---------------- helpers --------------------------------------------------
__device__ __forceinline__ void mma16816(float* c, const uint32_t* a, const uint32_t* b)
{
    asm volatile(
        "mma.sync.aligned.m16n8k16.row.col.f32.f16.f16.f32 "
        "{%0,%1,%2,%3}, {%4,%5,%6,%7}, {%8,%9}, {%0,%1,%2,%3};\n"
        : "+f"(c[0]), "+f"(c[1]), "+f"(c[2]), "+f"(c[3])
        : "r"(a[0]), "r"(a[1]), "r"(a[2]), "r"(a[3]), "r"(b[0]), "r"(b[1]));
}

__device__ __forceinline__ float ex2f(float x)
{
    float r;
    asm("ex2.approx.f32 %0, %1;" : "=f"(r) : "f"(x));
    return r;
}

__device__ __forceinline__ void cp_async16(void* s, const void* g)
{
    uint32_t sa = (uint32_t)__cvta_generic_to_shared(s);
    asm volatile("cp.async.cg.shared.global [%0], [%1], 16;\n" :: "r"(sa), "l"(g));
}

// ---------------- convert pass: fp32 -> fp16 -------------------------------
__global__ void cvt_kernel(const float4* __restrict__ src, uint2* __restrict__ dst, int n4)
{
    const int i = blockIdx.x * 256 + threadIdx.x;
    if (i >= n4) return;
    float4 v = src[i];
    __half2 a = __floats2half2_rn(v.x, v.y);
    __half2 b = __floats2half2_rn(v.z, v.w);
    uint2 o;
    o.x = *(const uint32_t*)&a;
    o.y = *(const uint32_t*)&b;
    dst[i] = o;
}

// ---------------- fp16 GEMM core (shared macro-ish structure) --------------
#define LDA 40                // padded row stride (halves): 80B = 20 banks
#define STG_ELEMS 7680        // per-stage halves: A 128*40 | B 64*40
#define GEMM_SMEM_BYTES (2 * STG_ELEMS * 2)

// GEMM mainloop: fills acc[2][4][4] for a 128x64 tile. Used by all variants.
#define GEMM_MAINLOOP(A_g, B_g, K)                                              \
    const int arow = tid >> 2;                                                  \
    const int ach  = (tid & 3) * 8;                                             \
    auto issue_stage = [&](int st, int k0) {                                    \
        __half* sa = smem + st * STG_ELEMS;                                     \
        __half* sb = sa + 5120;                                                 \
        _Pragma("unroll")                                                       \
        for (int rep = 0; rep < 2; rep++) {                                     \
            const int row = arow + rep * 64;                                    \
            cp_async16(&sa[row * LDA + ach], A_g + (size_t)(m0 + row) * K + k0 + ach); \
        }                                                                       \
        cp_async16(&sb[arow * LDA + ach], B_g + (size_t)(n0 + arow) * K + k0 + ach); \
        asm volatile("cp.async.commit_group;\n");                               \
    };                                                                          \
    const int KT = (K) >> 5;                                                    \
    issue_stage(0, 0);                                                          \
    for (int kt = 0; kt < KT; kt++) {                                           \
        if (kt + 1 < KT) {                                                      \
            issue_stage((kt + 1) & 1, (kt + 1) << 5);                           \
            asm volatile("cp.async.wait_group 1;\n");                           \
        } else {                                                                \
            asm volatile("cp.async.wait_group 0;\n");                           \
        }                                                                       \
        __syncthreads();                                                        \
        const __half* As = smem + (kt & 1) * STG_ELEMS;                         \
        const __half* Bs = As + 5120;                                           \
        _Pragma("unroll")                                                       \
        for (int kk = 0; kk < 32; kk += 16) {                                   \
            uint32_t af[2][4];                                                  \
            _Pragma("unroll")                                                   \
            for (int mi = 0; mi < 2; mi++) {                                    \
                const int r0 = (wm * 32 + mi * 16 + g) * LDA + kk + t * 2;      \
                const int r1 = r0 + 8 * LDA;                                    \
                af[mi][0] = *(const uint32_t*)&As[r0];                          \
                af[mi][1] = *(const uint32_t*)&As[r1];                          \
                af[mi][2] = *(const uint32_t*)&As[r0 + 8];                      \
                af[mi][3] = *(const uint32_t*)&As[r1 + 8];                      \
            }                                                                   \
            uint32_t bf[4][2];                                                  \
            _Pragma("unroll")                                                   \
            for (int ni = 0; ni < 4; ni++) {                                    \
                const int r = (wn * 32 + ni * 8 + g) * LDA + kk + t * 2;        \
                bf[ni][0] = *(const uint32_t*)&Bs[r];                           \
                bf[ni][1] = *(const uint32_t*)&Bs[r + 8];                       \
            }                                                                   \
            _Pragma("unroll")                                                   \
            for (int mi = 0; mi < 2; mi++)                                      \
                _Pragma("unroll")                                               \
                for (int ni = 0; ni < 4; ni++)                                  \
                    mma16816(acc[mi][ni], af[mi], bf[ni]);                      \
        }                                                                       \
        __syncthreads();                                                        \
    }

#define GEMM_PROLOG                                                             \
    extern __shared__ __half smem[];                                            \
    const int tid  = threadIdx.x;                                               \
    const int lane = tid & 31;                                                  \
    const int wid  = tid >> 5;                                                  \
    const int g    = lane >> 2;                                                 \
    const int t    = lane & 3;                                                  \
    const int wm   = wid >> 1;                                                  \
    const int wn   = wid & 1;                                                   \
    const int m0 = blockIdx.y * 128;                                            \
    const int n0 = blockIdx.x * 64;                                             \
    float acc[2][4][4];                                                         \
    _Pragma("unroll")                                                           \
    for (int mi = 0; mi < 2; mi++)                                              \
        _Pragma("unroll")                                                       \
        for (int ni = 0; ni < 4; ni++)                                          \
            _Pragma("unroll")                                                   \
            for (int e = 0; e < 4; e++) acc[mi][ni][e] = 0.f;

// ---- variant A: fp32 out, +bias[n] (se GEMM) ------------------------------
__global__ void __launch_bounds__(256, 2)
fgemm_bias(const __half* __restrict__ A_g, const __half* __restrict__ B_g,
           float* __restrict__ C, int N, int K, const float* __restrict__ bias)
{
    GEMM_PROLOG
    GEMM_MAINLOOP(A_g, B_g, K)

    #pragma unroll
    for (int mi = 0; mi < 2; mi++) {
        const int row0 = m0 + wm * 32 + mi * 16 + g;
        #pragma unroll
        for (int ni = 0; ni < 4; ni++) {
            const int col = n0 + wn * 32 + ni * 8 + t * 2;
            float2 bv = *(const float2*)(bias + col);
            float2 r01, r23;
            r01.x = acc[mi][ni][0] + bv.x; r01.y = acc[mi][ni][1] + bv.y;
            r23.x = acc[mi][ni][2] + bv.x; r23.y = acc[mi][ni][3] + bv.y;
            *(float2*)(C + (size_t)row0 * N + col)       = r01;
            *(float2*)(C + (size_t)(row0 + 8) * N + col) = r23;
        }
    }
}

// ---- variant B: qkv GEMM with fused per-head LN (q,k) + fp16 store --------
// block col range = exactly one head segment (64 cols). blockIdx.x<32 -> q/k.
__global__ void __launch_bounds__(256, 2)
fgemm_qkvln(const __half* __restrict__ A_g, const __half* __restrict__ B_g,
            __half* __restrict__ Cf, int N, int K)
{
    GEMM_PROLOG
    GEMM_MAINLOOP(A_g, B_g, K)

    const bool is_qk = (blockIdx.x < 32);
    float* red = (float*)smem;   // [wm][wn][rloc(32)][2] = 512 floats

    float mu_[2][2], rs_[2][2];
    if (is_qk) {
        #pragma unroll
        for (int mi = 0; mi < 2; mi++)
            #pragma unroll
            for (int rr = 0; rr < 2; rr++) {
                float s = 0.f, s2 = 0.f;
                #pragma unroll
                for (int ni = 0; ni < 4; ni++) {
                    const float v0 = acc[mi][ni][2 * rr + 0];
                    const float v1 = acc[mi][ni][2 * rr + 1];
                    s += v0 + v1; s2 += v0 * v0 + v1 * v1;
                }
                s  += __shfl_xor_sync(0xffffffffu, s, 1);
                s2 += __shfl_xor_sync(0xffffffffu, s2, 1);
                s  += __shfl_xor_sync(0xffffffffu, s, 2);
                s2 += __shfl_xor_sync(0xffffffffu, s2, 2);
                const int rloc = mi * 16 + rr * 8 + g;
                if (t == 0) {
                    red[(((wm * 2 + wn) * 32) + rloc) * 2 + 0] = s;
                    red[(((wm * 2 + wn) * 32) + rloc) * 2 + 1] = s2;
                }
            }
        __syncthreads();
        #pragma unroll
        for (int mi = 0; mi < 2; mi++)
            #pragma unroll
            for (int rr = 0; rr < 2; rr++) {
                const int rloc = mi * 16 + rr * 8 + g;
                const float s  = red[(((wm * 2 + 0) * 32) + rloc) * 2 + 0]
                               + red[(((wm * 2 + 1) * 32) + rloc) * 2 + 0];
                const float s2 = red[(((wm * 2 + 0) * 32) + rloc) * 2 + 1]
                               + red[(((wm * 2 + 1) * 32) + rloc) * 2 + 1];
                const float mu  = s * (1.f / 64.f);
                const float var = s2 * (1.f / 64.f) - mu * mu;
                mu_[mi][rr] = mu;
                rs_[mi][rr] = rsqrtf(var + EPSV);
            }
    } else {
        #pragma unroll
        for (int mi = 0; mi < 2; mi++)
            #pragma unroll
            for (int rr = 0; rr < 2; rr++) { mu_[mi][rr] = 0.f; rs_[mi][rr] = 1.f; }
    }

    #pragma unroll
    for (int mi = 0; mi < 2; mi++) {
        const int row0 = m0 + wm * 32 + mi * 16 + g;
        #pragma unroll
        for (int ni = 0; ni < 4; ni++) {
            const int col = n0 + wn * 32 + ni * 8 + t * 2;
            __half2 h0 = __floats2half2_rn(
                (acc[mi][ni][0] - mu_[mi][0]) * rs_[mi][0],
                (acc[mi][ni][1] - mu_[mi][0]) * rs_[mi][0]);
            __half2 h1 = __floats2half2_rn(
                (acc[mi][ni][2] - mu_[mi][1]) * rs_[mi][1],
                (acc[mi][ni][3] - mu_[mi][1]) * rs_[mi][1]);
            *(__half2*)(Cf + (size_t)row0 * N + col)       = h0;
            *(__half2*)(Cf + (size_t)(row0 + 8) * N + col) = h1;
        }
    }
}

// ---- variant C: fp32 out, + fp16 residual (out GEMM) ----------------------
__global__ void __launch_bounds__(256, 2)
fgemm_resid(const __half* __restrict__ A_g, const __half* __restrict__ B_g,
            float* __restrict__ C, int N, int K, const __half* __restrict__ resid)
{
    GEMM_PROLOG
    GEMM_MAINLOOP(A_g, B_g, K)

    #pragma unroll
    for (int mi = 0; mi < 2; mi++) {
        const int row0 = m0 + wm * 32 + mi * 16 + g;
        #pragma unroll
        for (int ni = 0; ni < 4; ni++) {
            const int col = n0 + wn * 32 + ni * 8 + t * 2;
            const size_t i0 = (size_t)row0 * N + col;
            const size_t i1 = (size_t)(row0 + 8) * N + col;
            float2 e0 = __half22float2(*(const __half2*)(resid + i0));
            float2 e1 = __half22float2(*(const __half2*)(resid + i1));
            float2 r01, r23;
            r01.x = acc[mi][ni][0] + e0.x; r01.y = acc[mi][ni][1] + e0.y;
            r23.x = acc[mi][ni][2] + e1.x; r23.y = acc[mi][ni][3] + e1.y;
            *(float2*)(C + i0) = r01;
            *(float2*)(C + i1) = r23;
        }
    }
}

// ---------------- LayerNorm(x)*(1+scale)+shift -> fp16 ---------------------
__global__ void ln_film_kernel(const float* __restrict__ x,
                               const float* __restrict__ se,
                               __half* __restrict__ hf)
{
    const int m = blockIdx.x;
    const float* xr = x + (size_t)m * CC;
    const float* sc = se + (size_t)m * (2 * CC);

    float v[4];
    float s = 0.f, s2 = 0.f;
    #pragma unroll
    for (int e = 0; e < 4; e++) {
        v[e] = xr[threadIdx.x + e * 256];
        s += v[e];
        s2 += v[e] * v[e];
    }
    __shared__ float shs[8], shs2[8], bcast[2];
    const int lane = threadIdx.x & 31, w = threadIdx.x >> 5;
    #pragma unroll
    for (int o = 16; o; o >>= 1) {
        s  += __shfl_xor_sync(0xffffffffu, s,  o);
        s2 += __shfl_xor_sync(0xffffffffu, s2, o);
    }
    if (lane == 0) { shs[w] = s; shs2[w] = s2; }
    __syncthreads();
    if (w == 0) {
        float a  = (lane < 8) ? shs[lane]  : 0.f;
        float a2 = (lane < 8) ? shs2[lane] : 0.f;
        #pragma unroll
        for (int o = 4; o; o >>= 1) {
            a  += __shfl_xor_sync(0xffffffffu, a,  o);
            a2 += __shfl_xor_sync(0xffffffffu, a2, o);
        }
        if (lane == 0) { bcast[0] = a; bcast[1] = a2; }
    }
    __syncthreads();
    const float mu  = bcast[0] * (1.f / CC);
    const float var = bcast[1] * (1.f / CC) - mu * mu;
    const float rs  = rsqrtf(var + EPSV);

    #pragma unroll
    for (int e = 0; e < 4; e++) {
        const int c = threadIdx.x + e * 256;
        const float hv = (v[e] - mu) * rs * (1.f + sc[c]) + sc[c + CC];
        hf[(size_t)m * CC + c] = __float2half_rn(hv);
    }
}

// ---------------- flash attention (fp16 mma) -------------------------------
#define FLD 72  // padded stride (halves): 144B = 36 banks; conflict-free frags

#define QF_OFF 0
#define KF_OFF (128 * FLD)
#define VF_OFF (KF_OFF + 64 * FLD)
#define FL_SMEM_BYTES ((VF_OFF + 64 * FLD) * 2)

__global__ void __launch_bounds__(256, 2)
flash_mma_kernel(const __half* __restrict__ qkvf,
                 __half* __restrict__ of)
{
    extern __shared__ __half sm[];
    __half* Qf = sm + QF_OFF;
    __half* Kf = sm + KF_OFF;
    __half* Vf = sm + VF_OFF;   // transposed: [d][pos]

    const int tid  = threadIdx.x;
    const int lane = tid & 31;
    const int wid  = tid >> 5;
    const int g    = lane >> 2;
    const int t    = lane & 3;

    const int b  = blockIdx.y >> 4;
    const int h  = blockIdx.y & 15;
    const int n0 = blockIdx.x * 128;

    const size_t hb_off = (size_t)b * NN * 3072 + h * 64;
    const __half* qg = qkvf + hb_off;
    const __half* kg = qg + 1024;
    const __half* vg = qg + 2048;

    // ---- load Q tile (128x64) ----
    {
        const int lr = tid >> 1;
        const int c0 = (tid & 1) * 32;
        #pragma unroll
        for (int i = 0; i < 4; i++) {
            const int c = c0 + i * 8;
            *(uint4*)&Qf[lr * FLD + c] = *(const uint4*)(qg + (size_t)(n0 + lr) * 3072 + c);
        }
    }

    float oacc[8][4];
    #pragma unroll
    for (int nb = 0; nb < 8; nb++)
        #pragma unroll
        for (int e = 0; e < 4; e++) oacc[nb][e] = 0.f;
    float m0r = -1e30f, m1r = -1e30f, l0r = 0.f, l1r = 0.f;

    const float scl = 0.125f * 1.44269504088896f;  // 1/sqrt(D) * log2(e)

    for (int kt = 0; kt < NN; kt += 64) {
        __syncthreads();
        // ---- load K (row-major) + V (transposed) tiles ----
        {
            const int lr = tid >> 2;
            const int c0 = (tid & 3) * 16;
            #pragma unroll
            for (int i = 0; i < 2; i++) {
                const int c = c0 + i * 8;
                *(uint4*)&Kf[lr * FLD + c] = *(const uint4*)(kg + (size_t)(kt + lr) * 3072 + c);
            }
            #pragma unroll
            for (int i = 0; i < 2; i++) {
                const int c = c0 + i * 8;
                uint4 pv = *(const uint4*)(vg + (size_t)(kt + lr) * 3072 + c);
                const __half* pb = (const __half*)&pv;
                #pragma unroll
                for (int j = 0; j < 8; j++)
                    Vf[(c + j) * FLD + lr] = pb[j];
            }
        }
        __syncthreads();

        // ---- S = Q K^T ----
        float sacc[8][4];
        #pragma unroll
        for (int nb = 0; nb < 8; nb++)
            #pragma unroll
            for (int e = 0; e < 4; e++) sacc[nb][e] = 0.f;

        #pragma unroll
        for (int kk = 0; kk < 4; kk++) {
            uint32_t af[4];
            const int ab = (wid * 16 + g) * FLD + kk * 16 + t * 2;
            af[0] = *(const uint32_t*)&Qf[ab];
            af[1] = *(const uint32_t*)&Qf[ab + 8 * FLD];
            af[2] = *(const uint32_t*)&Qf[ab + 8];
            af[3] = *(const uint32_t*)&Qf[ab + 8 * FLD + 8];
            #pragma unroll
            for (int nb = 0; nb < 8; nb++) {
                uint32_t bf[2];
                const int bbse = (nb * 8 + g) * FLD + kk * 16 + t * 2;
                bf[0] = *(const uint32_t*)&Kf[bbse];
                bf[1] = *(const uint32_t*)&Kf[bbse + 8];
                mma16816(sacc[nb], af, bf);
            }
        }

        // ---- online softmax ----
        float mx0 = -1e30f, mx1 = -1e30f;
        #pragma unroll
        for (int nb = 0; nb < 8; nb++) {
            sacc[nb][0] *= scl; sacc[nb][1] *= scl;
            sacc[nb][2] *= scl; sacc[nb][3] *= scl;
            mx0 = fmaxf(mx0, fmaxf(sacc[nb][0], sacc[nb][1]));
            mx1 = fmaxf(mx1, fmaxf(sacc[nb][2], sacc[nb][3]));
        }
        mx0 = fmaxf(mx0, __shfl_xor_sync(0xffffffffu, mx0, 1));
        mx0 = fmaxf(mx0, __shfl_xor_sync(0xffffffffu, mx0, 2));
        mx1 = fmaxf(mx1, __shfl_xor_sync(0xffffffffu, mx1, 1));
        mx1 = fmaxf(mx1, __shfl_xor_sync(0xffffffffu, mx1, 2));
        const float mn0 = fmaxf(m0r, mx0);
        const float mn1 = fmaxf(m1r, mx1);
        const float co0 = ex2f(m0r - mn0);
        const float co1 = ex2f(m1r - mn1);
        m0r = mn0; m1r = mn1;
        l0r *= co0; l1r *= co1;
        #pragma unroll
        for (int nb = 0; nb < 8; nb++) {
            oacc[nb][0] *= co0; oacc[nb][1] *= co0;
            oacc[nb][2] *= co1; oacc[nb][3] *= co1;
        }
        float rs0 = 0.f, rs1 = 0.f;
        #pragma unroll
        for (int nb = 0; nb < 8; nb++) {
            sacc[nb][0] = ex2f(sacc[nb][0] - mn0);
            sacc[nb][1] = ex2f(sacc[nb][1] - mn0);
            sacc[nb][2] = ex2f(sacc[nb][2] - mn1);
            sacc[nb][3] = ex2f(sacc[nb][3] - mn1);
            rs0 += sacc[nb][0] + sacc[nb][1];
            rs1 += sacc[nb][2] + sacc[nb][3];
        }
        rs0 += __shfl_xor_sync(0xffffffffu, rs0, 1);
        rs0 += __shfl_xor_sync(0xffffffffu, rs0, 2);
        rs1 += __shfl_xor_sync(0xffffffffu, rs1, 1);
        rs1 += __shfl_xor_sync(0xffffffffu, rs1, 2);
        l0r += rs0; l1r += rs1;

        // ---- O += P V ----
        #pragma unroll
        for (int kbk = 0; kbk < 4; kbk++) {
            uint32_t pa[4];
            #pragma unroll
            for (int half = 0; half < 2; half++) {
                __half2 hA = __floats2half2_rn(sacc[2 * kbk + half][0],
                                               sacc[2 * kbk + half][1]);
                __half2 hB = __floats2half2_rn(sacc[2 * kbk + half][2],
                                               sacc[2 * kbk + half][3]);
                pa[0 + 2 * half] = *(const uint32_t*)&hA;
                pa[1 + 2 * half] = *(const uint32_t*)&hB;
            }
            #pragma unroll
            for (int nb = 0; nb < 8; nb++) {
                uint32_t vf[2];
                const int vbse = (nb * 8 + g) * FLD + kbk * 16 + t * 2;
                vf[0] = *(const uint32_t*)&Vf[vbse];
                vf[1] = *(const uint32_t*)&Vf[vbse + 8];
                mma16816(oacc[nb], pa, vf);
            }
        }
    }

    // ---- epilogue: write of (fp16 only) ----
    const float inv0 = 1.f / l0r;
    const float inv1 = 1.f / l1r;
    const int row0 = n0 + wid * 16 + g;
    const int row1 = row0 + 8;
    const size_t obase = (size_t)b * NN * CC + h * 64;
    #pragma unroll
    for (int nb = 0; nb < 8; nb++) {
        const int col = nb * 8 + t * 2;
        __half2 f0 = __floats2half2_rn(oacc[nb][0] * inv0, oacc[nb][1] * inv0);
        __half2 f1 = __floats2half2_rn(oacc[nb][2] * inv1, oacc[nb][3] * inv1);
        *(__half2*)(of + obase + (size_t)row0 * CC + col) = f0;
        *(__half2*)(of + obase + (size_t)row1 * CC + col) = f1;
    }
}

// ---------------- launcher -------------------------------------------------
extern "C" void kernel_launch(void* const* d_in, const int* in_sizes, int n_in,
                              void* d_out, int out_size)
{
    const float* x      = (const float*)d_in[0];
    const float* emb    = (const float*)d_in[1];
    const float* W_emb  = (const float*)d_in[2];
    const float* b_emb  = (const float*)d_in[3];
    const float* W_proj = (const float*)d_in[4];
    const float* W_out  = (const float*)d_in[5];
    float* out = (float*)d_out;

    float *se;
    __half *embf, *hf, *qkvf, *of, *Wembf, *Wprjf, *Woutf;
    cudaGetSymbolAddress((void**)&se,    g_se);
    cudaGetSymbolAddress((void**)&embf,  g_embf);
    cudaGetSymbolAddress((void**)&hf,    g_hf);
    cudaGetSymbolAddress((void**)&qkvf,  g_qkvf);
    cudaGetSymbolAddress((void**)&of,    g_of);
    cudaGetSymbolAddress((void**)&Wembf, g_Wembf);
    cudaGetSymbolAddress((void**)&Wprjf, g_Wprjf);
    cudaGetSymbolAddress((void**)&Woutf, g_Woutf);

    cudaFuncSetAttribute(flash_mma_kernel,
                         cudaFuncAttributeMaxDynamicSharedMemorySize, FL_SMEM_BYTES);
    cudaFuncSetAttribute(fgemm_bias,
                         cudaFuncAttributeMaxDynamicSharedMemorySize, GEMM_SMEM_BYTES);
    cudaFuncSetAttribute(fgemm_qkvln,
                         cudaFuncAttributeMaxDynamicSharedMemorySize, GEMM_SMEM_BYTES);
    cudaFuncSetAttribute(fgemm_resid,
                         cudaFuncAttributeMaxDynamicSharedMemorySize, GEMM_SMEM_BYTES);

    // 0) convert inputs/weights to fp16
    cvt_kernel<<<(MM * 1024 / 4) / 256, 256>>>((const float4*)emb, (uint2*)embf, MM * 1024 / 4);
    cvt_kernel<<<(2048 * 1024 / 4) / 256, 256>>>((const float4*)W_emb, (uint2*)Wembf, 2048 * 1024 / 4);
    cvt_kernel<<<(3072 * 1024 / 4) / 256, 256>>>((const float4*)W_proj, (uint2*)Wprjf, 3072 * 1024 / 4);
    cvt_kernel<<<(1024 * 1024 / 4) / 256, 256>>>((const float4*)W_out, (uint2*)Woutf, 1024 * 1024 / 4);

    // 1) se = emb @ W_emb^T + b_emb   (fp32 out)
    fgemm_bias<<<dim3(2048 / 64, MM / 128), 256, GEMM_SMEM_BYTES>>>(
        embf, Wembf, se, 2048, EMB, b_emb);
    // 2) h = LN(x)*(1+scale)+shift -> fp16
    ln_film_kernel<<<MM, 256>>>(x, se, hf);
    // 3) qkv = h @ W_proj^T, fused q/k head-LN, fp16 out
    fgemm_qkvln<<<dim3(3072 / 64, MM / 128), 256, GEMM_SMEM_BYTES>>>(
        hf, Wprjf, qkvf, 3072, CC);
    // 4) flash attention -> of (fp16)
    flash_mma_kernel<<<dim3(NN / 128, BB * HH), 256, FL_SMEM_BYTES>>>(qkvf, of);
    // 5) out = of + of @ W_out^T  (fp32 out, fp16 residual)
    fgemm_resid<<<dim3(1024 / 64, MM / 128), 256, GEMM_SMEM_BYTES>>>(
        of, Woutf, out, 1024, CC, of);
}

// round 17
// speedup vs baseline: 8.3334x; 1.0505x over previous
#include <cuda_runtime.h>
#include <cuda_fp16.h>
#include <cstdint>

// Problem constants
#define BB 4
#define NN 2048
#define CC 1024
#define HH 16
#define DD 64
#define MM (BB*NN)          // 8192 token rows
#define EMB 1024
#define EPSV 1e-5f

// ---------------- scratch (device globals; no allocation allowed) ----------
__device__ float g_se [(size_t)MM * 2048];              // 64 MB
__device__ __half g_embf[(size_t)MM * 1024];            // 16 MB
__device__ __half g_hf  [(size_t)MM * 1024];            // 16 MB
__device__ __half g_qkvf[(size_t)MM * 3072];            // 48 MB
__device__ __half g_of  [(size_t)MM * 1024];            // 16 MB
__device__ __half g_Wembf[2048 * 1024];
__device__ __half g_Wprjf[3072 * 1024];
__device__ __half g_Woutf[1024 * 1024];

// ---------------- helpers --------------------------------------------------
__device__ __forceinline__ void mma16816(float* c, const uint32_t* a, const uint32_t* b)
{
    asm volatile(
        "mma.sync.aligned.m16n8k16.row.col.f32.f16.f16.f32 "
        "{%0,%1,%2,%3}, {%4,%5,%6,%7}, {%8,%9}, {%0,%1,%2,%3};\n"
        : "+f"(c[0]), "+f"(c[1]), "+f"(c[2]), "+f"(c[3])
        : "r"(a[0]), "r"(a[1]), "r"(a[2]), "r"(a[3]), "r"(b[0]), "r"(b[1]));
}

__device__ __forceinline__ float ex2f(float x)
{
    float r;
    asm("ex2.approx.f32 %0, %1;" : "=f"(r) : "f"(x));
    return r;
}

__device__ __forceinline__ void cp_async16(void* s, const void* g)
{
    uint32_t sa = (uint32_t)__cvta_generic_to_shared(s);
    asm volatile("cp.async.cg.shared.global [%0], [%1], 16;\n" :: "r"(sa), "l"(g));
}

// ---------------- convert pass: fp32 -> fp16 -------------------------------
__global__ void cvt_kernel(const float4* __restrict__ src, uint2* __restrict__ dst, int n4)
{
    const int i = blockIdx.x * 256 + threadIdx.x;
    if (i >= n4) return;
    float4 v = src[i];
    __half2 a = __floats2half2_rn(v.x, v.y);
    __half2 b = __floats2half2_rn(v.z, v.w);
    uint2 o;
    o.x = *(const uint32_t*)&a;
    o.y = *(const uint32_t*)&b;
    dst[i] = o;
}

// ---------------- fp16 GEMM core (shared macro-ish structure) --------------
#define LDA 40                // padded row stride (halves): 80B = 20 banks
#define STG_ELEMS 7680        // per-stage halves: A 128*40 | B 64*40
#define GEMM_SMEM_BYTES (2 * STG_ELEMS * 2)

#define GEMM_MAINLOOP(A_g, B_g, K)                                              \
    const int arow = tid >> 2;                                                  \
    const int ach  = (tid & 3) * 8;                                             \
    auto issue_stage = [&](int st, int k0) {                                    \
        __half* sa = smem + st * STG_ELEMS;                                     \
        __half* sb = sa + 5120;                                                 \
        _Pragma("unroll")                                                       \
        for (int rep = 0; rep < 2; rep++) {                                     \
            const int row = arow + rep * 64;                                    \
            cp_async16(&sa[row * LDA + ach], A_g + (size_t)(m0 + row) * K + k0 + ach); \
        }                                                                       \
        cp_async16(&sb[arow * LDA + ach], B_g + (size_t)(n0 + arow) * K + k0 + ach); \
        asm volatile("cp.async.commit_group;\n");                               \
    };                                                                          \
    const int KT = (K) >> 5;                                                    \
    issue_stage(0, 0);                                                          \
    for (int kt = 0; kt < KT; kt++) {                                           \
        if (kt + 1 < KT) {                                                      \
            issue_stage((kt + 1) & 1, (kt + 1) << 5);                           \
            asm volatile("cp.async.wait_group 1;\n");                           \
        } else {                                                                \
            asm volatile("cp.async.wait_group 0;\n");                           \
        }                                                                       \
        __syncthreads();                                                        \
        const __half* As = smem + (kt & 1) * STG_ELEMS;                         \
        const __half* Bs = As + 5120;                                           \
        _Pragma("unroll")                                                       \
        for (int kk = 0; kk < 32; kk += 16) {                                   \
            uint32_t af[2][4];                                                  \
            _Pragma("unroll")                                                   \
            for (int mi = 0; mi < 2; mi++) {                                    \
                const int r0 = (wm * 32 + mi * 16 + g) * LDA + kk + t * 2;      \
                const int r1 = r0 + 8 * LDA;                                    \
                af[mi][0] = *(const uint32_t*)&As[r0];                          \
                af[mi][1] = *(const uint32_t*)&As[r1];                          \
                af[mi][2] = *(const uint32_t*)&As[r0 + 8];                      \
                af[mi][3] = *(const uint32_t*)&As[r1 + 8];                      \
            }                                                                   \
            uint32_t bf[4][2];                                                  \
            _Pragma("unroll")                                                   \
            for (int ni = 0; ni < 4; ni++) {                                    \
                const int r = (wn * 32 + ni * 8 + g) * LDA + kk + t * 2;        \
                bf[ni][0] = *(const uint32_t*)&Bs[r];                           \
                bf[ni][1] = *(const uint32_t*)&Bs[r + 8];                       \
            }                                                                   \
            _Pragma("unroll")                                                   \
            for (int mi = 0; mi < 2; mi++)                                      \
                _Pragma("unroll")                                               \
                for (int ni = 0; ni < 4; ni++)                                  \
                    mma16816(acc[mi][ni], af[mi], bf[ni]);                      \
        }                                                                       \
        __syncthreads();                                                        \
    }

#define GEMM_PROLOG                                                             \
    extern __shared__ __half smem[];                                            \
    const int tid  = threadIdx.x;                                               \
    const int lane = tid & 31;                                                  \
    const int wid  = tid >> 5;                                                  \
    const int g    = lane >> 2;                                                 \
    const int t    = lane & 3;                                                  \
    const int wm   = wid >> 1;                                                  \
    const int wn   = wid & 1;                                                   \
    const int m0 = blockIdx.y * 128;                                            \
    const int n0 = blockIdx.x * 64;                                             \
    float acc[2][4][4];                                                         \
    _Pragma("unroll")                                                           \
    for (int mi = 0; mi < 2; mi++)                                              \
        _Pragma("unroll")                                                       \
        for (int ni = 0; ni < 4; ni++)                                          \
            _Pragma("unroll")                                                   \
            for (int e = 0; e < 4; e++) acc[mi][ni][e] = 0.f;

// ---- variant A: fp32 out, +bias[n] (se GEMM) ------------------------------
__global__ void __launch_bounds__(256, 2)
fgemm_bias(const __half* __restrict__ A_g, const __half* __restrict__ B_g,
           float* __restrict__ C, int N, int K, const float* __restrict__ bias)
{
    GEMM_PROLOG
    GEMM_MAINLOOP(A_g, B_g, K)

    #pragma unroll
    for (int mi = 0; mi < 2; mi++) {
        const int row0 = m0 + wm * 32 + mi * 16 + g;
        #pragma unroll
        for (int ni = 0; ni < 4; ni++) {
            const int col = n0 + wn * 32 + ni * 8 + t * 2;
            float2 bv = *(const float2*)(bias + col);
            float2 r01, r23;
            r01.x = acc[mi][ni][0] + bv.x; r01.y = acc[mi][ni][1] + bv.y;
            r23.x = acc[mi][ni][2] + bv.x; r23.y = acc[mi][ni][3] + bv.y;
            *(float2*)(C + (size_t)row0 * N + col)       = r01;
            *(float2*)(C + (size_t)(row0 + 8) * N + col) = r23;
        }
    }
}

// ---- variant B: qkv GEMM with fused per-head LN (q,k) + fp16 store --------
__global__ void __launch_bounds__(256, 2)
fgemm_qkvln(const __half* __restrict__ A_g, const __half* __restrict__ B_g,
            __half* __restrict__ Cf, int N, int K)
{
    GEMM_PROLOG
    GEMM_MAINLOOP(A_g, B_g, K)

    const bool is_qk = (blockIdx.x < 32);
    float* red = (float*)smem;   // [wm][wn][rloc(32)][2] = 512 floats

    float mu_[2][2], rs_[2][2];
    if (is_qk) {
        #pragma unroll
        for (int mi = 0; mi < 2; mi++)
            #pragma unroll
            for (int rr = 0; rr < 2; rr++) {
                float s = 0.f, s2 = 0.f;
                #pragma unroll
                for (int ni = 0; ni < 4; ni++) {
                    const float v0 = acc[mi][ni][2 * rr + 0];
                    const float v1 = acc[mi][ni][2 * rr + 1];
                    s += v0 + v1; s2 += v0 * v0 + v1 * v1;
                }
                s  += __shfl_xor_sync(0xffffffffu, s, 1);
                s2 += __shfl_xor_sync(0xffffffffu, s2, 1);
                s  += __shfl_xor_sync(0xffffffffu, s, 2);
                s2 += __shfl_xor_sync(0xffffffffu, s2, 2);
                const int rloc = mi * 16 + rr * 8 + g;
                if (t == 0) {
                    red[(((wm * 2 + wn) * 32) + rloc) * 2 + 0] = s;
                    red[(((wm * 2 + wn) * 32) + rloc) * 2 + 1] = s2;
                }
            }
        __syncthreads();
        #pragma unroll
        for (int mi = 0; mi < 2; mi++)
            #pragma unroll
            for (int rr = 0; rr < 2; rr++) {
                const int rloc = mi * 16 + rr * 8 + g;
                const float s  = red[(((wm * 2 + 0) * 32) + rloc) * 2 + 0]
                               + red[(((wm * 2 + 1) * 32) + rloc) * 2 + 0];
                const float s2 = red[(((wm * 2 + 0) * 32) + rloc) * 2 + 1]
                               + red[(((wm * 2 + 1) * 32) + rloc) * 2 + 1];
                const float mu  = s * (1.f / 64.f);
                const float var = s2 * (1.f / 64.f) - mu * mu;
                mu_[mi][rr] = mu;
                rs_[mi][rr] = rsqrtf(var + EPSV);
            }
    } else {
        #pragma unroll
        for (int mi = 0; mi < 2; mi++)
            #pragma unroll
            for (int rr = 0; rr < 2; rr++) { mu_[mi][rr] = 0.f; rs_[mi][rr] = 1.f; }
    }

    #pragma unroll
    for (int mi = 0; mi < 2; mi++) {
        const int row0 = m0 + wm * 32 + mi * 16 + g;
        #pragma unroll
        for (int ni = 0; ni < 4; ni++) {
            const int col = n0 + wn * 32 + ni * 8 + t * 2;
            __half2 h0 = __floats2half2_rn(
                (acc[mi][ni][0] - mu_[mi][0]) * rs_[mi][0],
                (acc[mi][ni][1] - mu_[mi][0]) * rs_[mi][0]);
            __half2 h1 = __floats2half2_rn(
                (acc[mi][ni][2] - mu_[mi][1]) * rs_[mi][1],
                (acc[mi][ni][3] - mu_[mi][1]) * rs_[mi][1]);
            *(__half2*)(Cf + (size_t)row0 * N + col)       = h0;
            *(__half2*)(Cf + (size_t)(row0 + 8) * N + col) = h1;
        }
    }
}

// ---- variant C: fp32 out, + fp16 residual (out GEMM) ----------------------
__global__ void __launch_bounds__(256, 2)
fgemm_resid(const __half* __restrict__ A_g, const __half* __restrict__ B_g,
            float* __restrict__ C, int N, int K, const __half* __restrict__ resid)
{
    GEMM_PROLOG
    GEMM_MAINLOOP(A_g, B_g, K)

    #pragma unroll
    for (int mi = 0; mi < 2; mi++) {
        const int row0 = m0 + wm * 32 + mi * 16 + g;
        #pragma unroll
        for (int ni = 0; ni < 4; ni++) {
            const int col = n0 + wn * 32 + ni * 8 + t * 2;
            const size_t i0 = (size_t)row0 * N + col;
            const size_t i1 = (size_t)(row0 + 8) * N + col;
            float2 e0 = __half22float2(*(const __half2*)(resid + i0));
            float2 e1 = __half22float2(*(const __half2*)(resid + i1));
            float2 r01, r23;
            r01.x = acc[mi][ni][0] + e0.x; r01.y = acc[mi][ni][1] + e0.y;
            r23.x = acc[mi][ni][2] + e1.x; r23.y = acc[mi][ni][3] + e1.y;
            *(float2*)(C + i0) = r01;
            *(float2*)(C + i1) = r23;
        }
    }
}

// ---------------- LayerNorm(x)*(1+scale)+shift -> fp16 ---------------------
__global__ void ln_film_kernel(const float* __restrict__ x,
                               const float* __restrict__ se,
                               __half* __restrict__ hf)
{
    const int m = blockIdx.x;
    const float* xr = x + (size_t)m * CC;
    const float* sc = se + (size_t)m * (2 * CC);

    float v[4];
    float s = 0.f, s2 = 0.f;
    #pragma unroll
    for (int e = 0; e < 4; e++) {
        v[e] = xr[threadIdx.x + e * 256];
        s += v[e];
        s2 += v[e] * v[e];
    }
    __shared__ float shs[8], shs2[8], bcast[2];
    const int lane = threadIdx.x & 31, w = threadIdx.x >> 5;
    #pragma unroll
    for (int o = 16; o; o >>= 1) {
        s  += __shfl_xor_sync(0xffffffffu, s,  o);
        s2 += __shfl_xor_sync(0xffffffffu, s2, o);
    }
    if (lane == 0) { shs[w] = s; shs2[w] = s2; }
    __syncthreads();
    if (w == 0) {
        float a  = (lane < 8) ? shs[lane]  : 0.f;
        float a2 = (lane < 8) ? shs2[lane] : 0.f;
        #pragma unroll
        for (int o = 4; o; o >>= 1) {
            a  += __shfl_xor_sync(0xffffffffu, a,  o);
            a2 += __shfl_xor_sync(0xffffffffu, a2, o);
        }
        if (lane == 0) { bcast[0] = a; bcast[1] = a2; }
    }
    __syncthreads();
    const float mu  = bcast[0] * (1.f / CC);
    const float var = bcast[1] * (1.f / CC) - mu * mu;
    const float rs  = rsqrtf(var + EPSV);

    #pragma unroll
    for (int e = 0; e < 4; e++) {
        const int c = threadIdx.x + e * 256;
        const float hv = (v[e] - mu) * rs * (1.f + sc[c]) + sc[c + CC];
        hf[(size_t)m * CC + c] = __float2half_rn(hv);
    }
}

// ---------------- flash attention (fp16 mma, fixed-max softmax) ------------
// |q.k| <= 64 (both LN'd, Cauchy-Schwarz) => |s*scl| <= 11.54.
// p = exp2(s*scl - 8): max ~11.6, min ~2^-19.5 — no overflow, shift cancels.
#define FLD 72  // padded stride (halves): 144B = 36 banks; conflict-free frags

#define QF_OFF 0
#define KST(s) (128 * FLD + (s) * 2 * 64 * FLD)
#define VST(s) (128 * FLD + (s) * 2 * 64 * FLD + 64 * FLD)
#define FL_SMEM_BYTES ((128 * FLD + 4 * 64 * FLD) * 2)

__global__ void __launch_bounds__(256, 2)
flash_mma_kernel(const __half* __restrict__ qkvf,
                 __half* __restrict__ of)
{
    extern __shared__ __half sm[];

    const int tid  = threadIdx.x;
    const int lane = tid & 31;
    const int wid  = tid >> 5;
    const int g    = lane >> 2;
    const int t    = lane & 3;

    const int b  = blockIdx.y >> 4;
    const int h  = blockIdx.y & 15;
    const int n0 = blockIdx.x * 128;

    const size_t hb_off = (size_t)b * NN * 3072 + h * 64;
    const __half* qg = qkvf + hb_off;
    const __half* kg = qg + 1024;
    const __half* vg = qg + 2048;

    // ---- load Q tile (128x64) ----
    {
        const int lr = tid >> 1;
        const int c0 = (tid & 1) * 32;
        #pragma unroll
        for (int i = 0; i < 4; i++) {
            const int c = c0 + i * 8;
            *(uint4*)&sm[QF_OFF + lr * FLD + c] =
                *(const uint4*)(qg + (size_t)(n0 + lr) * 3072 + c);
        }
    }

    const int lr = tid >> 2;           // 0..63 loader row
    const int c0 = (tid & 3) * 16;     // 0,16,32,48

    // prologue: K tile 0 via cp.async, V tile 0 into registers
    #pragma unroll
    for (int i = 0; i < 2; i++)
        cp_async16(&sm[KST(0) + lr * FLD + c0 + i * 8],
                   kg + (size_t)lr * 3072 + c0 + i * 8);
    asm volatile("cp.async.commit_group;\n");
    uint4 vr0 = *(const uint4*)(vg + (size_t)lr * 3072 + c0);
    uint4 vr1 = *(const uint4*)(vg + (size_t)lr * 3072 + c0 + 8);

    float oacc[8][4];
    #pragma unroll
    for (int nb = 0; nb < 8; nb++)
        #pragma unroll
        for (int e = 0; e < 4; e++) oacc[nb][e] = 0.f;
    float lsum0 = 0.f, lsum1 = 0.f;

    const float scl = 0.125f * 1.44269504088896f;  // 1/sqrt(D) * log2(e)

    const int NT = NN / 64;   // 32
    for (int it = 0; it < NT; it++) {
        const int st = it & 1;
        if (it + 1 < NT) {
            const size_t gnext = (size_t)((it + 1) * 64 + lr) * 3072 + c0;
            #pragma unroll
            for (int i = 0; i < 2; i++)
                cp_async16(&sm[KST(st ^ 1) + lr * FLD + c0 + i * 8],
                           kg + gnext + i * 8);
            asm volatile("cp.async.commit_group;\n");
            asm volatile("cp.async.wait_group 1;\n");
        } else {
            asm volatile("cp.async.wait_group 0;\n");
        }

        // store prefetched V registers (transposed) into stage st
        {
            const __half* pb = (const __half*)&vr0;
            #pragma unroll
            for (int j = 0; j < 8; j++)
                sm[VST(st) + (c0 + j) * FLD + lr] = pb[j];
            pb = (const __half*)&vr1;
            #pragma unroll
            for (int j = 0; j < 8; j++)
                sm[VST(st) + (c0 + 8 + j) * FLD + lr] = pb[j];
        }
        __syncthreads();

        // prefetch next V tile into registers (latency hidden by compute below)
        if (it + 1 < NT) {
            const size_t gnext = (size_t)((it + 1) * 64 + lr) * 3072 + c0;
            vr0 = *(const uint4*)(vg + gnext);
            vr1 = *(const uint4*)(vg + gnext + 8);
        }

        const __half* Qf = sm + QF_OFF;
        const __half* Kf = sm + KST(st);
        const __half* Vf = sm + VST(st);

        // ---- S = Q K^T ----
        float sacc[8][4];
        #pragma unroll
        for (int nb = 0; nb < 8; nb++)
            #pragma unroll
            for (int e = 0; e < 4; e++) sacc[nb][e] = 0.f;

        #pragma unroll
        for (int kk = 0; kk < 4; kk++) {
            uint32_t af[4];
            const int ab = (wid * 16 + g) * FLD + kk * 16 + t * 2;
            af[0] = *(const uint32_t*)&Qf[ab];
            af[1] = *(const uint32_t*)&Qf[ab + 8 * FLD];
            af[2] = *(const uint32_t*)&Qf[ab + 8];
            af[3] = *(const uint32_t*)&Qf[ab + 8 * FLD + 8];
            #pragma unroll
            for (int nb = 0; nb < 8; nb++) {
                uint32_t bf[2];
                const int bbse = (nb * 8 + g) * FLD + kk * 16 + t * 2;
                bf[0] = *(const uint32_t*)&Kf[bbse];
                bf[1] = *(const uint32_t*)&Kf[bbse + 8];
                mma16816(sacc[nb], af, bf);
            }
        }

        // ---- P = exp2(S*scl - 8); accumulate row sums (no max tracking) ----
        #pragma unroll
        for (int nb = 0; nb < 8; nb++) {
            sacc[nb][0] = ex2f(fmaf(sacc[nb][0], scl, -8.f));
            sacc[nb][1] = ex2f(fmaf(sacc[nb][1], scl, -8.f));
            sacc[nb][2] = ex2f(fmaf(sacc[nb][2], scl, -8.f));
            sacc[nb][3] = ex2f(fmaf(sacc[nb][3], scl, -8.f));
            lsum0 += sacc[nb][0] + sacc[nb][1];
            lsum1 += sacc[nb][2] + sacc[nb][3];
        }

        // ---- O += P V ----
        #pragma unroll
        for (int kbk = 0; kbk < 4; kbk++) {
            uint32_t pa[4];
            #pragma unroll
            for (int half = 0; half < 2; half++) {
                __half2 hA = __floats2half2_rn(sacc[2 * kbk + half][0],
                                               sacc[2 * kbk + half][1]);
                __half2 hB = __floats2half2_rn(sacc[2 * kbk + half][2],
                                               sacc[2 * kbk + half][3]);
                pa[0 + 2 * half] = *(const uint32_t*)&hA;
                pa[1 + 2 * half] = *(const uint32_t*)&hB;
            }
            #pragma unroll
            for (int nb = 0; nb < 8; nb++) {
                uint32_t vf[2];
                const int vbse = (nb * 8 + g) * FLD + kbk * 16 + t * 2;
                vf[0] = *(const uint32_t*)&Vf[vbse];
                vf[1] = *(const uint32_t*)&Vf[vbse + 8];
                mma16816(oacc[nb], pa, vf);
            }
        }
        __syncthreads();   // all warps done with stage st before it is refilled
    }

    // ---- final row-sum reduction (once, not per-iter) ----
    lsum0 += __shfl_xor_sync(0xffffffffu, lsum0, 1);
    lsum0 += __shfl_xor_sync(0xffffffffu, lsum0, 2);
    lsum1 += __shfl_xor_sync(0xffffffffu, lsum1, 1);
    lsum1 += __shfl_xor_sync(0xffffffffu, lsum1, 2);
    const float inv0 = 1.f / lsum0;
    const float inv1 = 1.f / lsum1;

    const int row0 = n0 + wid * 16 + g;
    const int row1 = row0 + 8;
    const size_t obase = (size_t)b * NN * CC + h * 64;
    #pragma unroll
    for (int nb = 0; nb < 8; nb++) {
        const int col = nb * 8 + t * 2;
        __half2 f0 = __floats2half2_rn(oacc[nb][0] * inv0, oacc[nb][1] * inv0);
        __half2 f1 = __floats2half2_rn(oacc[nb][2] * inv1, oacc[nb][3] * inv1);
        *(__half2*)(of + obase + (size_t)row0 * CC + col) = f0;
        *(__half2*)(of + obase + (size_t)row1 * CC + col) = f1;
    }
}

// ---------------- launcher -------------------------------------------------
extern "C" void kernel_launch(void* const* d_in, const int* in_sizes, int n_in,
                              void* d_out, int out_size)
{
    const float* x      = (const float*)d_in[0];
    const float* emb    = (const float*)d_in[1];
    const float* W_emb  = (const float*)d_in[2];
    const float* b_emb  = (const float*)d_in[3];
    const float* W_proj = (const float*)d_in[4];
    const float* W_out  = (const float*)d_in[5];
    float* out = (float*)d_out;

    float *se;
    __half *embf, *hf, *qkvf, *of, *Wembf, *Wprjf, *Woutf;
    cudaGetSymbolAddress((void**)&se,    g_se);
    cudaGetSymbolAddress((void**)&embf,  g_embf);
    cudaGetSymbolAddress((void**)&hf,    g_hf);
    cudaGetSymbolAddress((void**)&qkvf,  g_qkvf);
    cudaGetSymbolAddress((void**)&of,    g_of);
    cudaGetSymbolAddress((void**)&Wembf, g_Wembf);
    cudaGetSymbolAddress((void**)&Wprjf, g_Wprjf);
    cudaGetSymbolAddress((void**)&Woutf, g_Woutf);

    cudaFuncSetAttribute(flash_mma_kernel,
                         cudaFuncAttributeMaxDynamicSharedMemorySize, FL_SMEM_BYTES);
    cudaFuncSetAttribute(fgemm_bias,
                         cudaFuncAttributeMaxDynamicSharedMemorySize, GEMM_SMEM_BYTES);
    cudaFuncSetAttribute(fgemm_qkvln,
                         cudaFuncAttributeMaxDynamicSharedMemorySize, GEMM_SMEM_BYTES);
    cudaFuncSetAttribute(fgemm_resid,
                         cudaFuncAttributeMaxDynamicSharedMemorySize, GEMM_SMEM_BYTES);

    // 0) convert inputs/weights to fp16
    cvt_kernel<<<(MM * 1024 / 4) / 256, 256>>>((const float4*)emb, (uint2*)embf, MM * 1024 / 4);
    cvt_kernel<<<(2048 * 1024 / 4) / 256, 256>>>((const float4*)W_emb, (uint2*)Wembf, 2048 * 1024 / 4);
    cvt_kernel<<<(3072 * 1024 / 4) / 256, 256>>>((const float4*)W_proj, (uint2*)Wprjf, 3072 * 1024 / 4);
    cvt_kernel<<<(1024 * 1024 / 4) / 256, 256>>>((const float4*)W_out, (uint2*)Woutf, 1024 * 1024 / 4);

    // 1) se = emb @ W_emb^T + b_emb   (fp32 out)
    fgemm_bias<<<dim3(2048 / 64, MM / 128), 256, GEMM_SMEM_BYTES>>>(
        embf, Wembf, se, 2048, EMB, b_emb);
    // 2) h = LN(x)*(1+scale)+shift -> fp16
    ln_film_kernel<<<MM, 256>>>(x, se, hf);
    // 3) qkv = h @ W_proj^T, fused q/k head-LN, fp16 out
    fgemm_qkvln<<<dim3(3072 / 64, MM / 128), 256, GEMM_SMEM_BYTES>>>(
        hf, Wprjf, qkvf, 3072, CC);
    // 4) flash attention -> of (fp16)
    flash_mma_kernel<<<dim3(NN / 128, BB * HH), 256, FL_SMEM_BYTES>>>(qkvf, of);
    // 5) out = of + of @ W_out^T  (fp32 out, fp16 residual)
    fgemm_resid<<<dim3(1024 / 64, MM / 128), 256, GEMM_SMEM_BYTES>>>(
        of, Woutf, out, 1024, CC, of);
}